// round 13
// baseline (speedup 1.0000x reference)
#include <cuda_runtime.h>
#include <cuda_bf16.h>
#include <math.h>
#include <stdint.h>

// ---------------- problem constants ----------------
#define BATCH 512
#define HH 14
#define WW 14
#define DIN 512
#define EDIM 64
#define KCODES 256
#define NPIX (BATCH*HH*WW)          // 100352
#define NTOK (BATCH*4)              // 2048
#define H1 128                      // 2*EDIM

#define OUT_PPL ((size_t)NPIX*DIN)
#define OUT_CMT (OUT_PPL+1)
#define OUT_IDX (OUT_PPL+2)

// ---------------- scratch (static device memory; no allocations) ----------------
__device__ float g_Hbar[NTOK*H1];           // pooled SUMS (scaled by 1/49 in k_vq2)
__device__ float g_S[NTOK*DIN];
__device__ int   g_idx[NTOK];
__device__ int   g_counts[KCODES];
__device__ float g_loss;
// W1^T split into bf16 hi/lo: [n=128][k=512]
__device__ __nv_bfloat16 g_w1t_hi[H1*DIN];
__device__ __nv_bfloat16 g_w1t_lo[H1*DIN];

__device__ __forceinline__ float gelu_exact(float x) {
    return 0.5f * x * (1.0f + erff(x * 0.70710678118654752440f));
}

__device__ __forceinline__ uint32_t smem_u32(const void* p) {
    uint32_t a;
    asm("{ .reg .u64 t; cvta.to.shared.u64 t, %1; cvt.u32.u64 %0, t; }" : "=r"(a) : "l"(p));
    return a;
}

// baseline-PTX tensor ops (valid on plain sm_103 — no 'a' features)
__device__ __forceinline__ void ldsm_x4(uint32_t* r, uint32_t addr) {
    asm volatile("ldmatrix.sync.aligned.m8n8.x4.shared.b16 {%0,%1,%2,%3}, [%4];"
                 : "=r"(r[0]), "=r"(r[1]), "=r"(r[2]), "=r"(r[3]) : "r"(addr));
}
__device__ __forceinline__ void mma_bf16(float* d, const uint32_t* a, const uint32_t* b) {
    asm volatile("mma.sync.aligned.m16n8k16.row.col.f32.bf16.bf16.f32 "
                 "{%0,%1,%2,%3}, {%4,%5,%6,%7}, {%8,%9}, {%0,%1,%2,%3};"
                 : "+f"(d[0]), "+f"(d[1]), "+f"(d[2]), "+f"(d[3])
                 : "r"(a[0]), "r"(a[1]), "r"(a[2]), "r"(a[3]), "r"(b[0]), "r"(b[1]));
}
__device__ __forceinline__ uint32_t pk_bf16(__nv_bfloat16 a, __nv_bfloat16 b) {
    return (uint32_t)__bfloat16_as_ushort(a) | ((uint32_t)__bfloat16_as_ushort(b) << 16);
}
__device__ __forceinline__ void cp_async16(uint32_t dst, const void* src) {
    asm volatile("cp.async.ca.shared.global [%0], [%1], 16;" :: "r"(dst), "l"(src) : "memory");
}
#define CP_COMMIT()  asm volatile("cp.async.commit_group;" ::: "memory")
#define CP_WAIT0()   asm volatile("cp.async.wait_group 0;" ::: "memory")

// ---------------- kernel 0: setup (zero accumulators + Hbar, split W1^T) -----------
// grid 256 x 256 threads; exactly covers w1 (65536 elems) and Hbar (262144 floats).
__global__ __launch_bounds__(256) void k_setup(const float* __restrict__ w1) {
    int idx = blockIdx.x * 256 + threadIdx.x;
    // split W1^T
    int k = idx >> 7, n = idx & 127;
    float v = w1[idx];
    __nv_bfloat16 hi = __float2bfloat16(v);
    __nv_bfloat16 lo = __float2bfloat16(v - __bfloat162float(hi));
    g_w1t_hi[n * DIN + k] = hi;
    g_w1t_lo[n * DIN + k] = lo;
    // zero Hbar (4 floats per thread)
    *(float4*)&g_Hbar[idx * 4] = make_float4(0.f, 0.f, 0.f, 0.f);
    // zero small accumulators
    if (blockIdx.x == 0) {
        g_counts[threadIdx.x] = 0;
        if (threadIdx.x == 0) g_loss = 0.0f;
    }
}

// ---------------- kernel 1: delta -> split-bf16 HMMA GEMM (async pipeline) ---------
// Block: 128 pixels x 128 outputs. K=512 in 16 chunks of 32.
// All global loads via cp.async. A fp32 stage (single), bf16 tiles double-buffered.
// Tile pitch 80B (conflict-free ldmatrix: 80*i mod 128 -> 8 distinct 16B groups).
#define CH 32
#define NCH 16
#define TP 80
#define AST0 0u
#define AST1 16384u
#define TBUF0 32768u
#define TILE_SZ 10240u
#define TA_HI(b) (TBUF0 + (uint32_t)(b)*40960u)
#define TA_LO(b) (TA_HI(b) + TILE_SZ)
#define TB_HI(b) (TA_HI(b) + 2u*TILE_SZ)
#define TB_LO(b) (TA_HI(b) + 3u*TILE_SZ)
#define ENC_SM_BYTES (32768 + 2*40960)   // 114688 -> 2 blocks/SM
#define HS_PITCH 130                     // pooling tile (66560 B) reuses smem

__global__ __launch_bounds__(256, 2) void k_enc1(const float* __restrict__ t0,
                                                 const float* __restrict__ t1,
                                                 const float* __restrict__ b1) {
    extern __shared__ char sm[];
    const uint32_t smb = smem_u32(sm);
    float* Hs = (float*)sm;
    const int tid = threadIdx.x;
    const int wid = tid >> 5, l = tid & 31;
    const int wm = wid & 3, wn = wid >> 2;
    const int p0 = blockIdx.x * 128;

    float acc[2][8][4];
#pragma unroll
    for (int rt = 0; rt < 2; rt++)
#pragma unroll
        for (int nt = 0; nt < 8; nt++)
#pragma unroll
            for (int q = 0; q < 4; q++) acc[rt][nt][q] = 0.0f;

    const uint32_t a_row = (uint32_t)(wm * 32 + (l & 15));
    const uint32_t a_kof = (uint32_t)((l >> 4) * 16);
    const uint32_t b_row4 = (uint32_t)(wn * 64 + ((l >> 4) << 3) + (l & 7));
    const uint32_t b_k4   = (uint32_t)(((l >> 3) & 1) * 16);

    // staging coordinates (constant)
    const int bn = tid >> 2, bg = tid & 3;           // B: 2 iters of 256 -> 512 lines
    const int ar = tid >> 3, ag = tid & 7;           // A: 4 iters of 256 -> 1024 lines

    // ---- issue stage for chunk c into tile buffer tb (B direct, A -> fp32 stage) ----
    auto issue_stage = [&](int c, int tb) {
        const int kc = c * CH;
#pragma unroll
        for (int it = 0; it < 2; it++) {
            int n = bn + it * 64;                    // 0..127
            uint32_t off = (uint32_t)(n * TP + bg * 16);
            cp_async16(smb + TB_HI(tb) + off, g_w1t_hi + n * DIN + kc + bg * 8);
            cp_async16(smb + TB_LO(tb) + off, g_w1t_lo + n * DIN + kc + bg * 8);
        }
#pragma unroll
        for (int it = 0; it < 4; it++) {
            int row = ar + it * 32;                  // 0..127
            uint32_t off = (uint32_t)(row * 128 + ag * 16);
            size_t ga = (size_t)(p0 + row) * DIN + kc + ag * 4;
            cp_async16(smb + AST0 + off, t0 + ga);
            cp_async16(smb + AST1 + off, t1 + ga);
        }
        CP_COMMIT();
    };

    // ---- convert fp32 stage -> bf16 A tiles in buffer tb ----
    auto convert = [&](int tb) {
#pragma unroll
        for (int it = 0; it < 4; it++) {
            int row = ar + it * 32;
            uint32_t soff = (uint32_t)(row * 128 + ag * 16);
            float4 v1 = *(const float4*)(sm + AST1 + soff);
            float4 v0 = *(const float4*)(sm + AST0 + soff);
            float d0 = v1.x - v0.x, d1 = v1.y - v0.y, d2 = v1.z - v0.z, d3 = v1.w - v0.w;
            __nv_bfloat16 h0 = __float2bfloat16(d0), h1 = __float2bfloat16(d1),
                          h2 = __float2bfloat16(d2), h3 = __float2bfloat16(d3);
            __nv_bfloat16 e0 = __float2bfloat16(d0 - __bfloat162float(h0));
            __nv_bfloat16 e1 = __float2bfloat16(d1 - __bfloat162float(h1));
            __nv_bfloat16 e2 = __float2bfloat16(d2 - __bfloat162float(h2));
            __nv_bfloat16 e3 = __float2bfloat16(d3 - __bfloat162float(h3));
            uint32_t toff = (uint32_t)(row * TP + ag * 8);
            *(uint2*)(sm + TA_HI(tb) + toff) = make_uint2(pk_bf16(h0, h1), pk_bf16(h2, h3));
            *(uint2*)(sm + TA_LO(tb) + toff) = make_uint2(pk_bf16(e0, e1), pk_bf16(e2, e3));
        }
    };

    // ---- prologue: chunk 0 ----
    issue_stage(0, 0);
    CP_WAIT0();
    __syncthreads();        // B tiles + stage visible
    convert(0);
    __syncthreads();

    // ---- main loop ----
    for (int c = 0; c < NCH; c++) {
        const int buf = c & 1;
        if (c < NCH - 1) issue_stage(c + 1, buf ^ 1);

        // compute chunk c: 2 k16 steps
#pragma unroll
        for (int ks = 0; ks < 2; ks++) {
            uint32_t ahi[2][4], alo[2][4];
#pragma unroll
            for (int rt = 0; rt < 2; rt++) {
                uint32_t aoff = (a_row + rt * 16) * TP + ks * 32 + a_kof;
                ldsm_x4(ahi[rt], smb + TA_HI(buf) + aoff);
                ldsm_x4(alo[rt], smb + TA_LO(buf) + aoff);
            }
#pragma unroll
            for (int ntp = 0; ntp < 4; ntp++) {
                uint32_t boff = (b_row4 + ntp * 16) * TP + ks * 32 + b_k4;
                uint32_t bhi[4], blo[4];
                ldsm_x4(bhi, smb + TB_HI(buf) + boff);
                ldsm_x4(blo, smb + TB_LO(buf) + boff);
#pragma unroll
                for (int h = 0; h < 2; h++) {
                    int nt = ntp * 2 + h;
#pragma unroll
                    for (int rt = 0; rt < 2; rt++) {
                        mma_bf16(acc[rt][nt], ahi[rt], bhi + 2 * h);
                        mma_bf16(acc[rt][nt], ahi[rt], blo + 2 * h);
                        mma_bf16(acc[rt][nt], alo[rt], bhi + 2 * h);
                    }
                }
            }
        }

        if (c < NCH - 1) {
            CP_WAIT0();             // chunk c+1 copies landed (issued before compute)
            convert(buf ^ 1);       // stage -> A tiles (short, no long stalls)
        }
        __syncthreads();
    }

    // ---- epilogue: bias + GELU into smem tile, then fused 7x7 pooling ----
    float2 bias[8];
#pragma unroll
    for (int nt = 0; nt < 8; nt++) {
        int cc = wn * 64 + nt * 8 + 2 * (l & 3);
        bias[nt] = make_float2(__ldg(&b1[cc]), __ldg(&b1[cc + 1]));
    }
#pragma unroll
    for (int rt = 0; rt < 2; rt++) {
        int rl = wm * 32 + rt * 16 + (l >> 2);
#pragma unroll
        for (int nt = 0; nt < 8; nt++) {
            int cc = wn * 64 + nt * 8 + 2 * (l & 3);
            float2 o0, o1;
            o0.x = gelu_exact(acc[rt][nt][0] + bias[nt].x);
            o0.y = gelu_exact(acc[rt][nt][1] + bias[nt].y);
            o1.x = gelu_exact(acc[rt][nt][2] + bias[nt].x);
            o1.y = gelu_exact(acc[rt][nt][3] + bias[nt].y);
            *(float2*)&Hs[rl * HS_PITCH + cc]       = o0;
            *(float2*)&Hs[(rl + 8) * HS_PITCH + cc] = o1;
        }
    }
    __syncthreads();

    const int b0 = p0 / 196;
#pragma unroll
    for (int i = 0; i < 4; i++) {
        int pair = tid + i * 256;
        int slot = pair >> 7, col = pair & 127;
        int db = slot >> 2, ty = (slot >> 1) & 1, tx = slot & 1;
        int b = b0 + db;
        int base = b * 196 + ty * 98 + tx * 7 - p0;
        float s = 0.0f;
        int hit = 0;
#pragma unroll
        for (int dy = 0; dy < 7; dy++) {
            int rs = base + dy * 14;
            int lo = rs < 0 ? 0 : rs;
            int hi = rs + 7 > 128 ? 128 : rs + 7;
            for (int r = lo; r < hi; r++) { s += Hs[r * HS_PITCH + col]; hit = 1; }
        }
        if (hit) atomicAdd(&g_Hbar[(size_t)(b * 4 + ty * 2 + tx) * H1 + col], s);
    }
}

// ---------------- kernel 3: GEMM2 + VQ (8 tokens/block, 256 blocks) ----------------
#define VQ_TOKS 8
#define CBT_LD 257
#define FS_LD 65
#define SMEM_VQ_FLOATS (64*CBT_LD + VQ_TOKS*H1 + VQ_TOKS*FS_LD + KCODES + VQ_TOKS)
#define SMEM_VQ_BYTES (SMEM_VQ_FLOATS * 4)

__global__ __launch_bounds__(256) void k_vq2(const float* __restrict__ w2,
                                             const float* __restrict__ b2,
                                             const float* __restrict__ cb) {
    extern __shared__ float smv[];
    float* cbT   = smv;
    float* hbs   = cbT + 64 * CBT_LD;
    float* fs    = hbs + VQ_TOKS * H1;
    float* cn    = fs + VQ_TOKS * FS_LD;
    float* fnorm = cn + KCODES;

    const int tid = threadIdx.x;
    const int tok0 = blockIdx.x * VQ_TOKS;

    for (int li = tid; li < KCODES * EDIM; li += 256) {
        int c = li >> 6, j = li & 63;
        cbT[j * CBT_LD + c] = cb[li];
    }
    for (int li = tid; li < VQ_TOKS * H1; li += 256)
        hbs[li] = g_Hbar[tok0 * H1 + li] * (1.0f / 49.0f);
    __syncthreads();

    {
        float s = 0.0f;
#pragma unroll 8
        for (int j = 0; j < EDIM; j++) {
            float v = cbT[j * CBT_LD + tid];
            s = fmaf(v, v, s);
        }
        cn[tid] = s;
    }

    {
        const int j = tid & 63, tg = tid >> 6;
        float bj = b2[j];
        float acc0 = bj, acc1 = bj;
#pragma unroll 4
        for (int k = 0; k < H1; k++) {
            float wv = __ldg(&w2[k * EDIM + j]);
            acc0 = fmaf(hbs[(tg * 2 + 0) * H1 + k], wv, acc0);
            acc1 = fmaf(hbs[(tg * 2 + 1) * H1 + k], wv, acc1);
        }
        fs[(tg * 2 + 0) * FS_LD + j] = acc0;
        fs[(tg * 2 + 1) * FS_LD + j] = acc1;
    }
    __syncthreads();

    if (tid < VQ_TOKS) {
        float s = 0.0f;
#pragma unroll 8
        for (int j = 0; j < EDIM; j++) {
            float v = fs[tid * FS_LD + j];
            s = fmaf(v, v, s);
        }
        fnorm[tid] = s;
    }
    __syncthreads();

    const int w = tid >> 5, l = tid & 31;
    float dot[8];
#pragma unroll
    for (int i = 0; i < 8; i++) dot[i] = 0.0f;
#pragma unroll 4
    for (int j = 0; j < EDIM; j++) {
        float fj = fs[w * FS_LD + j];
#pragma unroll
        for (int i = 0; i < 8; i++)
            dot[i] = fmaf(fj, cbT[j * CBT_LD + l + 32 * i], dot[i]);
    }
    float bd = 3.4e38f; int bi = 0;
#pragma unroll
    for (int i = 0; i < 8; i++) {
        int c = l + 32 * i;
        float d = fmaf(-2.0f, dot[i], cn[c]);
        if (d < bd) { bd = d; bi = c; }
    }
    for (int off = 16; off > 0; off >>= 1) {
        float od = __shfl_down_sync(0xffffffffu, bd, off);
        int   oi = __shfl_down_sync(0xffffffffu, bi, off);
        if (od < bd || (od == bd && oi < bi)) { bd = od; bi = oi; }
    }
    if (l == 0) {
        int tok = tok0 + w;
        g_idx[tok] = bi;
        atomicAdd(&g_counts[bi], 1);
        atomicAdd(&g_loss, fnorm[w] + bd);
    }
}

// ---------------- kernel 4: perplexity + commitment + indices ----------------
__global__ __launch_bounds__(256) void k_fin(float* __restrict__ out) {
    __shared__ float r[256];
    int tid = threadIdx.x;
    float p = (float)g_counts[tid] * (1.0f / (float)NTOK);
    r[tid] = p * logf(p + 1e-10f);
    __syncthreads();
    for (int s = 128; s > 0; s >>= 1) {
        if (tid < s) r[tid] += r[tid + s];
        __syncthreads();
    }
    if (tid == 0) {
        out[OUT_PPL] = expf(-r[0]);
        out[OUT_CMT] = g_loss * (1.0f / (float)(NTOK * EDIM));
    }
    for (int i = tid; i < NTOK; i += 256) out[OUT_IDX + i] = (float)g_idx[i];
}

// ---------------- kernel 5: decoder MLP (8 tokens per block) ----------------
__global__ __launch_bounds__(256) void k_dec(const float* __restrict__ dw1,
                                             const float* __restrict__ db1,
                                             const float* __restrict__ dw2,
                                             const float* __restrict__ db2,
                                             const float* __restrict__ cb) {
    __shared__ float q[8][EDIM];
    __shared__ float hd[8][H1];
    int tid = threadIdx.x;
    int tb = blockIdx.x * 8;

    for (int li = tid; li < 8 * EDIM; li += 256) {
        int tt = li >> 6, j = li & 63;
        q[tt][j] = cb[g_idx[tb + tt] * EDIM + j];
    }
    __syncthreads();
#pragma unroll
    for (int i = 0; i < 4; i++) {
        int li = tid + i * 256;
        int tt = li >> 7, j = li & 127;
        float s = db1[j];
#pragma unroll 8
        for (int k = 0; k < EDIM; k++) s = fmaf(q[tt][k], dw1[k * H1 + j], s);
        hd[tt][j] = gelu_exact(s);
    }
    __syncthreads();

    float a0[8], a1[8];
#pragma unroll
    for (int tt = 0; tt < 8; tt++) { a0[tt] = 0.0f; a1[tt] = 0.0f; }
#pragma unroll 4
    for (int k = 0; k < H1; k++) {
        float w0 = dw2[k * DIN + tid];
        float w1v = dw2[k * DIN + 256 + tid];
#pragma unroll
        for (int tt = 0; tt < 8; tt++) {
            float h = hd[tt][k];
            a0[tt] = fmaf(h, w0, a0[tt]);
            a1[tt] = fmaf(h, w1v, a1[tt]);
        }
    }
    float bb0 = db2[tid], bb1 = db2[tid + 256];
#pragma unroll
    for (int tt = 0; tt < 8; tt++) {
        g_S[(size_t)(tb + tt) * DIN + tid]       = a0[tt] + bb0;
        g_S[(size_t)(tb + tt) * DIN + 256 + tid] = a1[tt] + bb1;
    }
}

// ---------------- kernel 6: 2x2 -> 14x14 bilinear ----------------
__global__ __launch_bounds__(256) void k_up(float* __restrict__ out) {
    __shared__ float Arow[DIN], Brow[DIN];
    int b = blockIdx.x, y = blockIdx.y;
    int tid = threadIdx.x;

    float sy = (y + 0.5f) * (1.0f / 7.0f) - 0.5f;
    int iy0 = (int)floorf(sy);
    float fy = sy - (float)iy0;
    int y0 = min(max(iy0, 0), 1);
    int y1 = min(max(iy0 + 1, 0), 1);

    const float* S0a = &g_S[(size_t)(b * 4 + y0 * 2 + 0) * DIN];
    const float* S1a = &g_S[(size_t)(b * 4 + y1 * 2 + 0) * DIN];
    const float* S0b = &g_S[(size_t)(b * 4 + y0 * 2 + 1) * DIN];
    const float* S1b = &g_S[(size_t)(b * 4 + y1 * 2 + 1) * DIN];
    float wy0 = 1.0f - fy;
    for (int c = tid; c < DIN; c += 256) {
        Arow[c] = wy0 * S0a[c] + fy * S1a[c];
        Brow[c] = wy0 * S0b[c] + fy * S1b[c];
    }
    __syncthreads();

#pragma unroll
    for (int x = 0; x < 14; x++) {
        float sx = (x + 0.5f) * (1.0f / 7.0f) - 0.5f;
        int ix0 = (int)floorf(sx);
        float fx = sx - (float)ix0;
        int x0 = min(max(ix0, 0), 1);
        int x1 = min(max(ix0 + 1, 0), 1);
        float wx0 = 1.0f - fx;
        float* o = out + ((size_t)((b * HH + y) * WW + x)) * DIN;
        for (int c = tid; c < DIN; c += 256) {
            float v0 = x0 ? Brow[c] : Arow[c];
            float v1 = x1 ? Brow[c] : Arow[c];
            o[c] = wx0 * v0 + fx * v1;
        }
    }
}

// ---------------- launch ----------------
extern "C" void kernel_launch(void* const* d_in, const int* in_sizes, int n_in,
                              void* d_out, int out_size) {
    const float* t0  = (const float*)d_in[0];
    const float* t1  = (const float*)d_in[1];
    const float* ew1 = (const float*)d_in[2];
    const float* eb1 = (const float*)d_in[3];
    const float* ew2 = (const float*)d_in[4];
    const float* eb2 = (const float*)d_in[5];
    const float* dw1 = (const float*)d_in[6];
    const float* db1 = (const float*)d_in[7];
    const float* dw2 = (const float*)d_in[8];
    const float* db2 = (const float*)d_in[9];
    const float* cb  = (const float*)d_in[10];
    float* out = (float*)d_out;

    cudaFuncSetAttribute(k_enc1, cudaFuncAttributeMaxDynamicSharedMemorySize, ENC_SM_BYTES);
    cudaFuncSetAttribute(k_vq2, cudaFuncAttributeMaxDynamicSharedMemorySize, SMEM_VQ_BYTES);

    k_setup<<<256, 256>>>(ew1);
    k_enc1<<<NPIX / 128, 256, ENC_SM_BYTES>>>(t0, t1, eb1);
    k_vq2<<<NTOK / VQ_TOKS, 256, SMEM_VQ_BYTES>>>(ew2, eb2, cb);
    k_fin<<<1, 256>>>(out);
    k_dec<<<NTOK / 8, 256>>>(dw1, db1, dw2, db2, cb);
    k_up<<<dim3(BATCH, HH), 256>>>(out);
}

// round 14
// speedup vs baseline: 1.7058x; 1.7058x over previous
#include <cuda_runtime.h>
#include <cuda_bf16.h>
#include <math.h>
#include <stdint.h>

// ---------------- problem constants ----------------
#define BATCH 512
#define HH 14
#define WW 14
#define DIN 512
#define EDIM 64
#define KCODES 256
#define NPIX (BATCH*HH*WW)          // 100352
#define NTOK (BATCH*4)              // 2048
#define H1 128                      // 2*EDIM

#define OUT_PPL ((size_t)NPIX*DIN)
#define OUT_CMT (OUT_PPL+1)
#define OUT_IDX (OUT_PPL+2)

// ---------------- scratch (static device memory; no allocations) ----------------
__device__ float g_Hbar[NTOK*H1];           // pooled SUMS (scaled by 1/49 in k_vq2)
__device__ float g_S[NTOK*DIN];
__device__ int   g_idx[NTOK];
__device__ int   g_counts[KCODES];
__device__ float g_loss;
// W1^T split into bf16 hi/lo: [n=128][k=512]
__device__ __nv_bfloat16 g_w1t_hi[H1*DIN];
__device__ __nv_bfloat16 g_w1t_lo[H1*DIN];

__device__ __forceinline__ float gelu_exact(float x) {
    return 0.5f * x * (1.0f + erff(x * 0.70710678118654752440f));
}

__device__ __forceinline__ uint32_t smem_u32(const void* p) {
    uint32_t a;
    asm("{ .reg .u64 t; cvta.to.shared.u64 t, %1; cvt.u32.u64 %0, t; }" : "=r"(a) : "l"(p));
    return a;
}

// baseline-PTX tensor ops (valid on plain sm_103 — no 'a' features)
__device__ __forceinline__ void ldsm_x4(uint32_t* r, uint32_t addr) {
    asm volatile("ldmatrix.sync.aligned.m8n8.x4.shared.b16 {%0,%1,%2,%3}, [%4];"
                 : "=r"(r[0]), "=r"(r[1]), "=r"(r[2]), "=r"(r[3]) : "r"(addr));
}
__device__ __forceinline__ void mma_bf16(float* d, const uint32_t* a, const uint32_t* b) {
    asm volatile("mma.sync.aligned.m16n8k16.row.col.f32.bf16.bf16.f32 "
                 "{%0,%1,%2,%3}, {%4,%5,%6,%7}, {%8,%9}, {%0,%1,%2,%3};"
                 : "+f"(d[0]), "+f"(d[1]), "+f"(d[2]), "+f"(d[3])
                 : "r"(a[0]), "r"(a[1]), "r"(a[2]), "r"(a[3]), "r"(b[0]), "r"(b[1]));
}
__device__ __forceinline__ uint32_t pk_bf16(__nv_bfloat16 a, __nv_bfloat16 b) {
    return (uint32_t)__bfloat16_as_ushort(a) | ((uint32_t)__bfloat16_as_ushort(b) << 16);
}
__device__ __forceinline__ void cp_async16(uint32_t dst, const void* src) {
    asm volatile("cp.async.ca.shared.global [%0], [%1], 16;" :: "r"(dst), "l"(src) : "memory");
}
#define CP_COMMIT()  asm volatile("cp.async.commit_group;" ::: "memory")
#define CP_WAIT0()   asm volatile("cp.async.wait_group 0;" ::: "memory")

// ---------------- kernel 0: setup (zero accumulators + Hbar, split W1^T) -----------
// grid 256 x 256 threads; covers w1 (65536 elems) and Hbar (262144 floats).
__global__ __launch_bounds__(256) void k_setup(const float* __restrict__ w1) {
    int idx = blockIdx.x * 256 + threadIdx.x;
    int k = idx >> 7, n = idx & 127;
    float v = w1[idx];
    __nv_bfloat16 hi = __float2bfloat16(v);
    __nv_bfloat16 lo = __float2bfloat16(v - __bfloat162float(hi));
    g_w1t_hi[n * DIN + k] = hi;
    g_w1t_lo[n * DIN + k] = lo;
    *(float4*)&g_Hbar[idx * 4] = make_float4(0.f, 0.f, 0.f, 0.f);
    if (blockIdx.x == 0) {
        g_counts[threadIdx.x] = 0;
        if (threadIdx.x == 0) g_loss = 0.0f;
    }
}

// ---------------- kernel 1: delta -> split-bf16 HMMA GEMM -> GELU -> fused pool ----
// (R11 configuration: single-buffer, K-chunks of 64, LDG staging + cp.async B,
//  2 blocks/SM, fused 7x7 pooling. This is the measured-best enc1: 145.4 us.)
#define SM_AHI 0
#define SM_ALO (128*144)
#define SM_BHI (2*128*144)
#define SM_BLO (3*128*144)
#define ENC_SM_BYTES (4*128*144)   // 73728
#define HS_PITCH 130

__global__ __launch_bounds__(256, 2) void k_enc1(const float* __restrict__ t0,
                                                 const float* __restrict__ t1,
                                                 const float* __restrict__ b1) {
    extern __shared__ char sm[];
    const uint32_t smb = smem_u32(sm);
    float* Hs = (float*)sm;
    const int tid = threadIdx.x;
    const int wid = tid >> 5, l = tid & 31;
    const int wm = wid & 3, wn = wid >> 2;
    const int p0 = blockIdx.x * 128;

    float acc[2][8][4];
#pragma unroll
    for (int rt = 0; rt < 2; rt++)
#pragma unroll
        for (int nt = 0; nt < 8; nt++)
#pragma unroll
            for (int q = 0; q < 4; q++) acc[rt][nt][q] = 0.0f;

    const uint32_t a_row = (uint32_t)(wm * 32 + (l & 15));
    const uint32_t a_kof = (uint32_t)((l >> 4) * 16);
    const uint32_t b_row4 = (uint32_t)(wn * 64 + ((l >> 4) << 3) + (l & 7));
    const uint32_t b_k4   = (uint32_t)(((l >> 3) & 1) * 16);

    for (int c = 0; c < 8; c++) {
        const int kc = c * 64;
        if (c) __syncthreads();
#pragma unroll
        for (int it = 0; it < 4; it++) {
            int i = tid + it * 256;
            int n = i >> 3, g = i & 7;
            uint32_t off = (uint32_t)(n * 144 + g * 16);
            cp_async16(smb + SM_BHI + off, g_w1t_hi + n * DIN + kc + g * 8);
            cp_async16(smb + SM_BLO + off, g_w1t_lo + n * DIN + kc + g * 8);
        }
        CP_COMMIT();
#pragma unroll
        for (int half = 0; half < 4; half++) {
            float4 v1[2], v0[2];
            int rows[2], gs[2];
#pragma unroll
            for (int u = 0; u < 2; u++) {
                int i = tid + (half * 2 + u) * 256;
                rows[u] = i >> 4; gs[u] = i & 15;
                size_t gaddr = (size_t)(p0 + rows[u]) * DIN + kc + gs[u] * 4;
                v1[u] = *(const float4*)(t1 + gaddr);
                v0[u] = *(const float4*)(t0 + gaddr);
            }
#pragma unroll
            for (int u = 0; u < 2; u++) {
                float d0 = v1[u].x - v0[u].x, d1 = v1[u].y - v0[u].y,
                      d2 = v1[u].z - v0[u].z, d3 = v1[u].w - v0[u].w;
                __nv_bfloat16 h0 = __float2bfloat16(d0), h1 = __float2bfloat16(d1),
                              h2 = __float2bfloat16(d2), h3 = __float2bfloat16(d3);
                __nv_bfloat16 e0 = __float2bfloat16(d0 - __bfloat162float(h0));
                __nv_bfloat16 e1 = __float2bfloat16(d1 - __bfloat162float(h1));
                __nv_bfloat16 e2 = __float2bfloat16(d2 - __bfloat162float(h2));
                __nv_bfloat16 e3 = __float2bfloat16(d3 - __bfloat162float(h3));
                uint32_t off = (uint32_t)(rows[u] * 144 + gs[u] * 8);
                *(uint2*)(sm + SM_AHI + off) = make_uint2(pk_bf16(h0, h1), pk_bf16(h2, h3));
                *(uint2*)(sm + SM_ALO + off) = make_uint2(pk_bf16(e0, e1), pk_bf16(e2, e3));
            }
        }
        CP_WAIT0();
        __syncthreads();
#pragma unroll
        for (int ks = 0; ks < 4; ks++) {
            uint32_t ahi[2][4], alo[2][4];
#pragma unroll
            for (int rt = 0; rt < 2; rt++) {
                uint32_t aoff = (a_row + rt * 16) * 144 + ks * 32 + a_kof;
                ldsm_x4(ahi[rt], smb + SM_AHI + aoff);
                ldsm_x4(alo[rt], smb + SM_ALO + aoff);
            }
#pragma unroll
            for (int ntp = 0; ntp < 4; ntp++) {
                uint32_t boff = (b_row4 + ntp * 16) * 144 + ks * 32 + b_k4;
                uint32_t bhi[4], blo[4];
                ldsm_x4(bhi, smb + SM_BHI + boff);
                ldsm_x4(blo, smb + SM_BLO + boff);
#pragma unroll
                for (int h = 0; h < 2; h++) {
                    int nt = ntp * 2 + h;
#pragma unroll
                    for (int rt = 0; rt < 2; rt++) {
                        mma_bf16(acc[rt][nt], ahi[rt], bhi + 2 * h);
                        mma_bf16(acc[rt][nt], ahi[rt], blo + 2 * h);
                        mma_bf16(acc[rt][nt], alo[rt], bhi + 2 * h);
                    }
                }
            }
        }
    }

    // ---- epilogue: bias + GELU into smem tile (reuses A/B tile space) ----
    float2 bias[8];
#pragma unroll
    for (int nt = 0; nt < 8; nt++) {
        int cc = wn * 64 + nt * 8 + 2 * (l & 3);
        bias[nt] = make_float2(__ldg(&b1[cc]), __ldg(&b1[cc + 1]));
    }
    __syncthreads();     // all ldsm consumers done before overwriting tiles
#pragma unroll
    for (int rt = 0; rt < 2; rt++) {
        int rl = wm * 32 + rt * 16 + (l >> 2);
#pragma unroll
        for (int nt = 0; nt < 8; nt++) {
            int cc = wn * 64 + nt * 8 + 2 * (l & 3);
            float2 o0, o1;
            o0.x = gelu_exact(acc[rt][nt][0] + bias[nt].x);
            o0.y = gelu_exact(acc[rt][nt][1] + bias[nt].y);
            o1.x = gelu_exact(acc[rt][nt][2] + bias[nt].x);
            o1.y = gelu_exact(acc[rt][nt][3] + bias[nt].y);
            *(float2*)&Hs[rl * HS_PITCH + cc]       = o0;
            *(float2*)&Hs[(rl + 8) * HS_PITCH + cc] = o1;
        }
    }
    __syncthreads();

    // ---- fused 7x7 pooling: 8 token slots x 128 channels, 4 pairs/thread ----
    const int b0 = p0 / 196;
#pragma unroll
    for (int i = 0; i < 4; i++) {
        int pair = tid + i * 256;
        int slot = pair >> 7, col = pair & 127;
        int db = slot >> 2, ty = (slot >> 1) & 1, tx = slot & 1;
        int b = b0 + db;
        int base = b * 196 + ty * 98 + tx * 7 - p0;
        float s = 0.0f;
        int hit = 0;
#pragma unroll
        for (int dy = 0; dy < 7; dy++) {
            int rs = base + dy * 14;
            int lo = rs < 0 ? 0 : rs;
            int hi = rs + 7 > 128 ? 128 : rs + 7;
            for (int r = lo; r < hi; r++) { s += Hs[r * HS_PITCH + col]; hit = 1; }
        }
        if (hit) atomicAdd(&g_Hbar[(size_t)(b * 4 + ty * 2 + tx) * H1 + col], s);
    }
}

// ---------------- kernel 3: GEMM2 + VQ (8 tokens/block, 256 blocks) ----------------
#define VQ_TOKS 8
#define CBT_LD 257
#define FS_LD 65
#define SMEM_VQ_FLOATS (64*CBT_LD + VQ_TOKS*H1 + VQ_TOKS*FS_LD + KCODES + VQ_TOKS)
#define SMEM_VQ_BYTES (SMEM_VQ_FLOATS * 4)

__global__ __launch_bounds__(256) void k_vq2(const float* __restrict__ w2,
                                             const float* __restrict__ b2,
                                             const float* __restrict__ cb) {
    extern __shared__ float smv[];
    float* cbT   = smv;
    float* hbs   = cbT + 64 * CBT_LD;
    float* fs    = hbs + VQ_TOKS * H1;
    float* cn    = fs + VQ_TOKS * FS_LD;
    float* fnorm = cn + KCODES;

    const int tid = threadIdx.x;
    const int tok0 = blockIdx.x * VQ_TOKS;

    for (int li = tid; li < KCODES * EDIM; li += 256) {
        int c = li >> 6, j = li & 63;
        cbT[j * CBT_LD + c] = cb[li];
    }
    for (int li = tid; li < VQ_TOKS * H1; li += 256)
        hbs[li] = g_Hbar[tok0 * H1 + li] * (1.0f / 49.0f);
    __syncthreads();

    {
        float s = 0.0f;
#pragma unroll 8
        for (int j = 0; j < EDIM; j++) {
            float v = cbT[j * CBT_LD + tid];
            s = fmaf(v, v, s);
        }
        cn[tid] = s;
    }

    {
        const int j = tid & 63, tg = tid >> 6;
        float bj = b2[j];
        float acc0 = bj, acc1 = bj;
#pragma unroll 4
        for (int k = 0; k < H1; k++) {
            float wv = __ldg(&w2[k * EDIM + j]);
            acc0 = fmaf(hbs[(tg * 2 + 0) * H1 + k], wv, acc0);
            acc1 = fmaf(hbs[(tg * 2 + 1) * H1 + k], wv, acc1);
        }
        fs[(tg * 2 + 0) * FS_LD + j] = acc0;
        fs[(tg * 2 + 1) * FS_LD + j] = acc1;
    }
    __syncthreads();

    if (tid < VQ_TOKS) {
        float s = 0.0f;
#pragma unroll 8
        for (int j = 0; j < EDIM; j++) {
            float v = fs[tid * FS_LD + j];
            s = fmaf(v, v, s);
        }
        fnorm[tid] = s;
    }
    __syncthreads();

    const int w = tid >> 5, l = tid & 31;
    float dot[8];
#pragma unroll
    for (int i = 0; i < 8; i++) dot[i] = 0.0f;
#pragma unroll 4
    for (int j = 0; j < EDIM; j++) {
        float fj = fs[w * FS_LD + j];
#pragma unroll
        for (int i = 0; i < 8; i++)
            dot[i] = fmaf(fj, cbT[j * CBT_LD + l + 32 * i], dot[i]);
    }
    float bd = 3.4e38f; int bi = 0;
#pragma unroll
    for (int i = 0; i < 8; i++) {
        int c = l + 32 * i;
        float d = fmaf(-2.0f, dot[i], cn[c]);
        if (d < bd) { bd = d; bi = c; }
    }
    for (int off = 16; off > 0; off >>= 1) {
        float od = __shfl_down_sync(0xffffffffu, bd, off);
        int   oi = __shfl_down_sync(0xffffffffu, bi, off);
        if (od < bd || (od == bd && oi < bi)) { bd = od; bi = oi; }
    }
    if (l == 0) {
        int tok = tok0 + w;
        g_idx[tok] = bi;
        atomicAdd(&g_counts[bi], 1);
        atomicAdd(&g_loss, fnorm[w] + bd);
    }
}

// ---------------- kernel 5: decoder MLP (8 tokens/block) + fused finalize ----------
__global__ __launch_bounds__(256) void k_dec(const float* __restrict__ dw1,
                                             const float* __restrict__ db1,
                                             const float* __restrict__ dw2,
                                             const float* __restrict__ db2,
                                             const float* __restrict__ cb,
                                             float* __restrict__ out) {
    __shared__ float q[8][EDIM];
    __shared__ float hd[8][H1];
    int tid = threadIdx.x;
    int tb = blockIdx.x * 8;

    for (int li = tid; li < 8 * EDIM; li += 256) {
        int tt = li >> 6, j = li & 63;
        q[tt][j] = cb[g_idx[tb + tt] * EDIM + j];
    }
    __syncthreads();
#pragma unroll
    for (int i = 0; i < 4; i++) {
        int li = tid + i * 256;
        int tt = li >> 7, j = li & 127;
        float s = db1[j];
#pragma unroll 8
        for (int k = 0; k < EDIM; k++) s = fmaf(q[tt][k], dw1[k * H1 + j], s);
        hd[tt][j] = gelu_exact(s);
    }
    __syncthreads();

    float a0[8], a1[8];
#pragma unroll
    for (int tt = 0; tt < 8; tt++) { a0[tt] = 0.0f; a1[tt] = 0.0f; }
#pragma unroll 4
    for (int k = 0; k < H1; k++) {
        float w0 = dw2[k * DIN + tid];
        float w1v = dw2[k * DIN + 256 + tid];
#pragma unroll
        for (int tt = 0; tt < 8; tt++) {
            float h = hd[tt][k];
            a0[tt] = fmaf(h, w0, a0[tt]);
            a1[tt] = fmaf(h, w1v, a1[tt]);
        }
    }
    float bb0 = db2[tid], bb1 = db2[tid + 256];
#pragma unroll
    for (int tt = 0; tt < 8; tt++) {
        g_S[(size_t)(tb + tt) * DIN + tid]       = a0[tt] + bb0;
        g_S[(size_t)(tb + tt) * DIN + 256 + tid] = a1[tt] + bb1;
    }

    // ---- fused finalize (block 0 only): perplexity + commitment + indices ----
    if (blockIdx.x == 0) {
        __shared__ float r[256];
        float p = (float)g_counts[tid] * (1.0f / (float)NTOK);
        r[tid] = p * logf(p + 1e-10f);
        __syncthreads();
        for (int s = 128; s > 0; s >>= 1) {
            if (tid < s) r[tid] += r[tid + s];
            __syncthreads();
        }
        if (tid == 0) {
            out[OUT_PPL] = expf(-r[0]);
            out[OUT_CMT] = g_loss * (1.0f / (float)(NTOK * EDIM));
        }
        for (int i = tid; i < NTOK; i += 256) out[OUT_IDX + i] = (float)g_idx[i];
    }
}

// ---------------- kernel 6: 2x2 -> 14x14 bilinear ----------------
__global__ __launch_bounds__(256) void k_up(float* __restrict__ out) {
    __shared__ float Arow[DIN], Brow[DIN];
    int b = blockIdx.x, y = blockIdx.y;
    int tid = threadIdx.x;

    float sy = (y + 0.5f) * (1.0f / 7.0f) - 0.5f;
    int iy0 = (int)floorf(sy);
    float fy = sy - (float)iy0;
    int y0 = min(max(iy0, 0), 1);
    int y1 = min(max(iy0 + 1, 0), 1);

    const float* S0a = &g_S[(size_t)(b * 4 + y0 * 2 + 0) * DIN];
    const float* S1a = &g_S[(size_t)(b * 4 + y1 * 2 + 0) * DIN];
    const float* S0b = &g_S[(size_t)(b * 4 + y0 * 2 + 1) * DIN];
    const float* S1b = &g_S[(size_t)(b * 4 + y1 * 2 + 1) * DIN];
    float wy0 = 1.0f - fy;
    for (int c = tid; c < DIN; c += 256) {
        Arow[c] = wy0 * S0a[c] + fy * S1a[c];
        Brow[c] = wy0 * S0b[c] + fy * S1b[c];
    }
    __syncthreads();

#pragma unroll
    for (int x = 0; x < 14; x++) {
        float sx = (x + 0.5f) * (1.0f / 7.0f) - 0.5f;
        int ix0 = (int)floorf(sx);
        float fx = sx - (float)ix0;
        int x0 = min(max(ix0, 0), 1);
        int x1 = min(max(ix0 + 1, 0), 1);
        float wx0 = 1.0f - fx;
        float* o = out + ((size_t)((b * HH + y) * WW + x)) * DIN;
        for (int c = tid; c < DIN; c += 256) {
            float v0 = x0 ? Brow[c] : Arow[c];
            float v1 = x1 ? Brow[c] : Arow[c];
            o[c] = wx0 * v0 + fx * v1;
        }
    }
}

// ---------------- launch ----------------
extern "C" void kernel_launch(void* const* d_in, const int* in_sizes, int n_in,
                              void* d_out, int out_size) {
    const float* t0  = (const float*)d_in[0];
    const float* t1  = (const float*)d_in[1];
    const float* ew1 = (const float*)d_in[2];
    const float* eb1 = (const float*)d_in[3];
    const float* ew2 = (const float*)d_in[4];
    const float* eb2 = (const float*)d_in[5];
    const float* dw1 = (const float*)d_in[6];
    const float* db1 = (const float*)d_in[7];
    const float* dw2 = (const float*)d_in[8];
    const float* db2 = (const float*)d_in[9];
    const float* cb  = (const float*)d_in[10];
    float* out = (float*)d_out;

    cudaFuncSetAttribute(k_enc1, cudaFuncAttributeMaxDynamicSharedMemorySize, ENC_SM_BYTES);
    cudaFuncSetAttribute(k_vq2, cudaFuncAttributeMaxDynamicSharedMemorySize, SMEM_VQ_BYTES);

    k_setup<<<256, 256>>>(ew1);
    k_enc1<<<NPIX / 128, 256, ENC_SM_BYTES>>>(t0, t1, eb1);
    k_vq2<<<NTOK / VQ_TOKS, 256, SMEM_VQ_BYTES>>>(ew2, eb2, cb);
    k_dec<<<NTOK / 8, 256>>>(dw1, db1, dw2, db2, cb, out);
    k_up<<<dim3(BATCH, HH), 256>>>(out);
}

// round 15
// speedup vs baseline: 1.7642x; 1.0342x over previous
#include <cuda_runtime.h>
#include <cuda_bf16.h>
#include <math.h>
#include <stdint.h>

// ---------------- problem constants ----------------
#define BATCH 512
#define HH 14
#define WW 14
#define DIN 512
#define EDIM 64
#define KCODES 256
#define NPIX (BATCH*HH*WW)          // 100352
#define NTOK (BATCH*4)              // 2048
#define H1 128                      // 2*EDIM

#define OUT_PPL ((size_t)NPIX*DIN)
#define OUT_CMT (OUT_PPL+1)
#define OUT_IDX (OUT_PPL+2)

// ---------------- scratch (static device memory; no allocations) ----------------
__device__ float g_Hbar[NTOK*H1];           // pooled SUMS (scaled by 1/49 in k_vq2)
__device__ float g_S[NTOK*DIN];
__device__ int   g_idx[NTOK];
__device__ int   g_counts[KCODES];
__device__ float g_loss;
// W1^T split into bf16 hi/lo: [n=128][k=512]
__device__ __nv_bfloat16 g_w1t_hi[H1*DIN];
__device__ __nv_bfloat16 g_w1t_lo[H1*DIN];

__device__ __forceinline__ float gelu_exact(float x) {
    return 0.5f * x * (1.0f + erff(x * 0.70710678118654752440f));
}

__device__ __forceinline__ uint32_t smem_u32(const void* p) {
    uint32_t a;
    asm("{ .reg .u64 t; cvta.to.shared.u64 t, %1; cvt.u32.u64 %0, t; }" : "=r"(a) : "l"(p));
    return a;
}

// baseline-PTX tensor ops (valid on plain sm_103 — no 'a' features)
__device__ __forceinline__ void ldsm_x4(uint32_t* r, uint32_t addr) {
    asm volatile("ldmatrix.sync.aligned.m8n8.x4.shared.b16 {%0,%1,%2,%3}, [%4];"
                 : "=r"(r[0]), "=r"(r[1]), "=r"(r[2]), "=r"(r[3]) : "r"(addr));
}
__device__ __forceinline__ void mma_bf16(float* d, const uint32_t* a, const uint32_t* b) {
    asm volatile("mma.sync.aligned.m16n8k16.row.col.f32.bf16.bf16.f32 "
                 "{%0,%1,%2,%3}, {%4,%5,%6,%7}, {%8,%9}, {%0,%1,%2,%3};"
                 : "+f"(d[0]), "+f"(d[1]), "+f"(d[2]), "+f"(d[3])
                 : "r"(a[0]), "r"(a[1]), "r"(a[2]), "r"(a[3]), "r"(b[0]), "r"(b[1]));
}
__device__ __forceinline__ uint32_t pk_bf16(__nv_bfloat16 a, __nv_bfloat16 b) {
    return (uint32_t)__bfloat16_as_ushort(a) | ((uint32_t)__bfloat16_as_ushort(b) << 16);
}
__device__ __forceinline__ void cp_async16(uint32_t dst, const void* src) {
    asm volatile("cp.async.ca.shared.global [%0], [%1], 16;" :: "r"(dst), "l"(src) : "memory");
}
#define CP_COMMIT()  asm volatile("cp.async.commit_group;" ::: "memory")
#define CP_WAIT0()   asm volatile("cp.async.wait_group 0;" ::: "memory")

// ---------------- kernel 0: setup (zero accumulators + Hbar, split W1^T) -----------
__global__ __launch_bounds__(256) void k_setup(const float* __restrict__ w1) {
    int idx = blockIdx.x * 256 + threadIdx.x;
    int k = idx >> 7, n = idx & 127;
    float v = w1[idx];
    __nv_bfloat16 hi = __float2bfloat16(v);
    __nv_bfloat16 lo = __float2bfloat16(v - __bfloat162float(hi));
    g_w1t_hi[n * DIN + k] = hi;
    g_w1t_lo[n * DIN + k] = lo;
    *(float4*)&g_Hbar[idx * 4] = make_float4(0.f, 0.f, 0.f, 0.f);
    if (blockIdx.x == 0) {
        g_counts[threadIdx.x] = 0;
        if (threadIdx.x == 0) g_loss = 0.0f;
    }
}

// ---------------- kernel 1: delta -> split-bf16 HMMA GEMM -> GELU -> fused pool ----
// (R11/R14 measured-best configuration — DO NOT grow registers or smem.)
#define SM_AHI 0
#define SM_ALO (128*144)
#define SM_BHI (2*128*144)
#define SM_BLO (3*128*144)
#define ENC_SM_BYTES (4*128*144)   // 73728
#define HS_PITCH 130

__global__ __launch_bounds__(256, 2) void k_enc1(const float* __restrict__ t0,
                                                 const float* __restrict__ t1,
                                                 const float* __restrict__ b1) {
    extern __shared__ char sm[];
    const uint32_t smb = smem_u32(sm);
    float* Hs = (float*)sm;
    const int tid = threadIdx.x;
    const int wid = tid >> 5, l = tid & 31;
    const int wm = wid & 3, wn = wid >> 2;
    const int p0 = blockIdx.x * 128;

    float acc[2][8][4];
#pragma unroll
    for (int rt = 0; rt < 2; rt++)
#pragma unroll
        for (int nt = 0; nt < 8; nt++)
#pragma unroll
            for (int q = 0; q < 4; q++) acc[rt][nt][q] = 0.0f;

    const uint32_t a_row = (uint32_t)(wm * 32 + (l & 15));
    const uint32_t a_kof = (uint32_t)((l >> 4) * 16);
    const uint32_t b_row4 = (uint32_t)(wn * 64 + ((l >> 4) << 3) + (l & 7));
    const uint32_t b_k4   = (uint32_t)(((l >> 3) & 1) * 16);

    for (int c = 0; c < 8; c++) {
        const int kc = c * 64;
        if (c) __syncthreads();
#pragma unroll
        for (int it = 0; it < 4; it++) {
            int i = tid + it * 256;
            int n = i >> 3, g = i & 7;
            uint32_t off = (uint32_t)(n * 144 + g * 16);
            cp_async16(smb + SM_BHI + off, g_w1t_hi + n * DIN + kc + g * 8);
            cp_async16(smb + SM_BLO + off, g_w1t_lo + n * DIN + kc + g * 8);
        }
        CP_COMMIT();
#pragma unroll
        for (int half = 0; half < 4; half++) {
            float4 v1[2], v0[2];
            int rows[2], gs[2];
#pragma unroll
            for (int u = 0; u < 2; u++) {
                int i = tid + (half * 2 + u) * 256;
                rows[u] = i >> 4; gs[u] = i & 15;
                size_t gaddr = (size_t)(p0 + rows[u]) * DIN + kc + gs[u] * 4;
                v1[u] = *(const float4*)(t1 + gaddr);
                v0[u] = *(const float4*)(t0 + gaddr);
            }
#pragma unroll
            for (int u = 0; u < 2; u++) {
                float d0 = v1[u].x - v0[u].x, d1 = v1[u].y - v0[u].y,
                      d2 = v1[u].z - v0[u].z, d3 = v1[u].w - v0[u].w;
                __nv_bfloat16 h0 = __float2bfloat16(d0), h1 = __float2bfloat16(d1),
                              h2 = __float2bfloat16(d2), h3 = __float2bfloat16(d3);
                __nv_bfloat16 e0 = __float2bfloat16(d0 - __bfloat162float(h0));
                __nv_bfloat16 e1 = __float2bfloat16(d1 - __bfloat162float(h1));
                __nv_bfloat16 e2 = __float2bfloat16(d2 - __bfloat162float(h2));
                __nv_bfloat16 e3 = __float2bfloat16(d3 - __bfloat162float(h3));
                uint32_t off = (uint32_t)(rows[u] * 144 + gs[u] * 8);
                *(uint2*)(sm + SM_AHI + off) = make_uint2(pk_bf16(h0, h1), pk_bf16(h2, h3));
                *(uint2*)(sm + SM_ALO + off) = make_uint2(pk_bf16(e0, e1), pk_bf16(e2, e3));
            }
        }
        CP_WAIT0();
        __syncthreads();
#pragma unroll
        for (int ks = 0; ks < 4; ks++) {
            uint32_t ahi[2][4], alo[2][4];
#pragma unroll
            for (int rt = 0; rt < 2; rt++) {
                uint32_t aoff = (a_row + rt * 16) * 144 + ks * 32 + a_kof;
                ldsm_x4(ahi[rt], smb + SM_AHI + aoff);
                ldsm_x4(alo[rt], smb + SM_ALO + aoff);
            }
#pragma unroll
            for (int ntp = 0; ntp < 4; ntp++) {
                uint32_t boff = (b_row4 + ntp * 16) * 144 + ks * 32 + b_k4;
                uint32_t bhi[4], blo[4];
                ldsm_x4(bhi, smb + SM_BHI + boff);
                ldsm_x4(blo, smb + SM_BLO + boff);
#pragma unroll
                for (int h = 0; h < 2; h++) {
                    int nt = ntp * 2 + h;
#pragma unroll
                    for (int rt = 0; rt < 2; rt++) {
                        mma_bf16(acc[rt][nt], ahi[rt], bhi + 2 * h);
                        mma_bf16(acc[rt][nt], ahi[rt], blo + 2 * h);
                        mma_bf16(acc[rt][nt], alo[rt], bhi + 2 * h);
                    }
                }
            }
        }
    }

    float2 bias[8];
#pragma unroll
    for (int nt = 0; nt < 8; nt++) {
        int cc = wn * 64 + nt * 8 + 2 * (l & 3);
        bias[nt] = make_float2(__ldg(&b1[cc]), __ldg(&b1[cc + 1]));
    }
    __syncthreads();
#pragma unroll
    for (int rt = 0; rt < 2; rt++) {
        int rl = wm * 32 + rt * 16 + (l >> 2);
#pragma unroll
        for (int nt = 0; nt < 8; nt++) {
            int cc = wn * 64 + nt * 8 + 2 * (l & 3);
            float2 o0, o1;
            o0.x = gelu_exact(acc[rt][nt][0] + bias[nt].x);
            o0.y = gelu_exact(acc[rt][nt][1] + bias[nt].y);
            o1.x = gelu_exact(acc[rt][nt][2] + bias[nt].x);
            o1.y = gelu_exact(acc[rt][nt][3] + bias[nt].y);
            *(float2*)&Hs[rl * HS_PITCH + cc]       = o0;
            *(float2*)&Hs[(rl + 8) * HS_PITCH + cc] = o1;
        }
    }
    __syncthreads();

    const int b0 = p0 / 196;
#pragma unroll
    for (int i = 0; i < 4; i++) {
        int pair = tid + i * 256;
        int slot = pair >> 7, col = pair & 127;
        int db = slot >> 2, ty = (slot >> 1) & 1, tx = slot & 1;
        int b = b0 + db;
        int base = b * 196 + ty * 98 + tx * 7 - p0;
        float s = 0.0f;
        int hit = 0;
#pragma unroll
        for (int dy = 0; dy < 7; dy++) {
            int rs = base + dy * 14;
            int lo = rs < 0 ? 0 : rs;
            int hi = rs + 7 > 128 ? 128 : rs + 7;
            for (int r = lo; r < hi; r++) { s += Hs[r * HS_PITCH + col]; hit = 1; }
        }
        if (hit) atomicAdd(&g_Hbar[(size_t)(b * 4 + ty * 2 + tx) * H1 + col], s);
    }
}

// ---------------- kernel 3: GEMM2 + VQ (8 tokens/block, 256 blocks) ----------------
#define VQ_TOKS 8
#define CBT_LD 257
#define FS_LD 65
#define SMEM_VQ_FLOATS (64*CBT_LD + VQ_TOKS*H1 + VQ_TOKS*FS_LD + KCODES + VQ_TOKS)
#define SMEM_VQ_BYTES (SMEM_VQ_FLOATS * 4)

__global__ __launch_bounds__(256) void k_vq2(const float* __restrict__ w2,
                                             const float* __restrict__ b2,
                                             const float* __restrict__ cb) {
    extern __shared__ float smv[];
    float* cbT   = smv;
    float* hbs   = cbT + 64 * CBT_LD;
    float* fs    = hbs + VQ_TOKS * H1;
    float* cn    = fs + VQ_TOKS * FS_LD;
    float* fnorm = cn + KCODES;

    const int tid = threadIdx.x;
    const int tok0 = blockIdx.x * VQ_TOKS;

    for (int li = tid; li < KCODES * EDIM; li += 256) {
        int c = li >> 6, j = li & 63;
        cbT[j * CBT_LD + c] = cb[li];
    }
    for (int li = tid; li < VQ_TOKS * H1; li += 256)
        hbs[li] = g_Hbar[tok0 * H1 + li] * (1.0f / 49.0f);
    __syncthreads();

    {
        float s = 0.0f;
#pragma unroll 8
        for (int j = 0; j < EDIM; j++) {
            float v = cbT[j * CBT_LD + tid];
            s = fmaf(v, v, s);
        }
        cn[tid] = s;
    }

    {
        const int j = tid & 63, tg = tid >> 6;
        float bj = b2[j];
        float acc0 = bj, acc1 = bj;
#pragma unroll 4
        for (int k = 0; k < H1; k++) {
            float wv = __ldg(&w2[k * EDIM + j]);
            acc0 = fmaf(hbs[(tg * 2 + 0) * H1 + k], wv, acc0);
            acc1 = fmaf(hbs[(tg * 2 + 1) * H1 + k], wv, acc1);
        }
        fs[(tg * 2 + 0) * FS_LD + j] = acc0;
        fs[(tg * 2 + 1) * FS_LD + j] = acc1;
    }
    __syncthreads();

    if (tid < VQ_TOKS) {
        float s = 0.0f;
#pragma unroll 8
        for (int j = 0; j < EDIM; j++) {
            float v = fs[tid * FS_LD + j];
            s = fmaf(v, v, s);
        }
        fnorm[tid] = s;
    }
    __syncthreads();

    const int w = tid >> 5, l = tid & 31;
    float dot[8];
#pragma unroll
    for (int i = 0; i < 8; i++) dot[i] = 0.0f;
#pragma unroll 4
    for (int j = 0; j < EDIM; j++) {
        float fj = fs[w * FS_LD + j];
#pragma unroll
        for (int i = 0; i < 8; i++)
            dot[i] = fmaf(fj, cbT[j * CBT_LD + l + 32 * i], dot[i]);
    }
    float bd = 3.4e38f; int bi = 0;
#pragma unroll
    for (int i = 0; i < 8; i++) {
        int c = l + 32 * i;
        float d = fmaf(-2.0f, dot[i], cn[c]);
        if (d < bd) { bd = d; bi = c; }
    }
    for (int off = 16; off > 0; off >>= 1) {
        float od = __shfl_down_sync(0xffffffffu, bd, off);
        int   oi = __shfl_down_sync(0xffffffffu, bi, off);
        if (od < bd || (od == bd && oi < bi)) { bd = od; bi = oi; }
    }
    if (l == 0) {
        int tok = tok0 + w;
        g_idx[tok] = bi;
        atomicAdd(&g_counts[bi], 1);
        atomicAdd(&g_loss, fnorm[w] + bd);
    }
}

// ---------------- kernel 5: decoder MLP (split over DIN halves) + fused finalize ----
// grid (256, 2): blockIdx.x = token group (8 tokens), blockIdx.y = 256-col half.
// Each block recomputes q+hd (cheap) and owns one 256-wide output strip:
// 1 column/thread, 8 accumulators, unroll-8 over k -> high MLP.
__global__ __launch_bounds__(256) void k_dec(const float* __restrict__ dw1,
                                             const float* __restrict__ db1,
                                             const float* __restrict__ dw2,
                                             const float* __restrict__ db2,
                                             const float* __restrict__ cb,
                                             float* __restrict__ out) {
    __shared__ float q[8][EDIM];
    __shared__ float hd[8][H1];
    int tid = threadIdx.x;
    int tb = blockIdx.x * 8;
    int col = blockIdx.y * 256 + tid;

    for (int li = tid; li < 8 * EDIM; li += 256) {
        int tt = li >> 6, j = li & 63;
        q[tt][j] = cb[g_idx[tb + tt] * EDIM + j];
    }
    __syncthreads();
#pragma unroll
    for (int i = 0; i < 4; i++) {
        int li = tid + i * 256;
        int tt = li >> 7, j = li & 127;
        float s = db1[j];
#pragma unroll 8
        for (int k = 0; k < EDIM; k++) s = fmaf(q[tt][k], dw1[k * H1 + j], s);
        hd[tt][j] = gelu_exact(s);
    }
    __syncthreads();

    float a[8];
#pragma unroll
    for (int tt = 0; tt < 8; tt++) a[tt] = 0.0f;
#pragma unroll 8
    for (int k = 0; k < H1; k++) {
        float w = __ldg(&dw2[k * DIN + col]);
#pragma unroll
        for (int tt = 0; tt < 8; tt++) a[tt] = fmaf(hd[tt][k], w, a[tt]);
    }
    float bb = __ldg(&db2[col]);
#pragma unroll
    for (int tt = 0; tt < 8; tt++)
        g_S[(size_t)(tb + tt) * DIN + col] = a[tt] + bb;

    // ---- fused finalize (block (0,0) only) ----
    if (blockIdx.x == 0 && blockIdx.y == 0) {
        __shared__ float r[256];
        float p = (float)g_counts[tid] * (1.0f / (float)NTOK);
        r[tid] = p * logf(p + 1e-10f);
        __syncthreads();
        for (int s = 128; s > 0; s >>= 1) {
            if (tid < s) r[tid] += r[tid + s];
            __syncthreads();
        }
        if (tid == 0) {
            out[OUT_PPL] = expf(-r[0]);
            out[OUT_CMT] = g_loss * (1.0f / (float)(NTOK * EDIM));
        }
        for (int i = tid; i < NTOK; i += 256) out[OUT_IDX + i] = (float)g_idx[i];
    }
}

// ---------------- kernel 6: 2x2 -> 14x14 bilinear ----------------
__global__ __launch_bounds__(256) void k_up(float* __restrict__ out) {
    __shared__ float Arow[DIN], Brow[DIN];
    int b = blockIdx.x, y = blockIdx.y;
    int tid = threadIdx.x;

    float sy = (y + 0.5f) * (1.0f / 7.0f) - 0.5f;
    int iy0 = (int)floorf(sy);
    float fy = sy - (float)iy0;
    int y0 = min(max(iy0, 0), 1);
    int y1 = min(max(iy0 + 1, 0), 1);

    const float* S0a = &g_S[(size_t)(b * 4 + y0 * 2 + 0) * DIN];
    const float* S1a = &g_S[(size_t)(b * 4 + y1 * 2 + 0) * DIN];
    const float* S0b = &g_S[(size_t)(b * 4 + y0 * 2 + 1) * DIN];
    const float* S1b = &g_S[(size_t)(b * 4 + y1 * 2 + 1) * DIN];
    float wy0 = 1.0f - fy;
    for (int c = tid; c < DIN; c += 256) {
        Arow[c] = wy0 * S0a[c] + fy * S1a[c];
        Brow[c] = wy0 * S0b[c] + fy * S1b[c];
    }
    __syncthreads();

#pragma unroll
    for (int x = 0; x < 14; x++) {
        float sx = (x + 0.5f) * (1.0f / 7.0f) - 0.5f;
        int ix0 = (int)floorf(sx);
        float fx = sx - (float)ix0;
        int x0 = min(max(ix0, 0), 1);
        int x1 = min(max(ix0 + 1, 0), 1);
        float wx0 = 1.0f - fx;
        float* o = out + ((size_t)((b * HH + y) * WW + x)) * DIN;
        for (int c = tid; c < DIN; c += 256) {
            float v0 = x0 ? Brow[c] : Arow[c];
            float v1 = x1 ? Brow[c] : Arow[c];
            o[c] = wx0 * v0 + fx * v1;
        }
    }
}

// ---------------- launch ----------------
extern "C" void kernel_launch(void* const* d_in, const int* in_sizes, int n_in,
                              void* d_out, int out_size) {
    const float* t0  = (const float*)d_in[0];
    const float* t1  = (const float*)d_in[1];
    const float* ew1 = (const float*)d_in[2];
    const float* eb1 = (const float*)d_in[3];
    const float* ew2 = (const float*)d_in[4];
    const float* eb2 = (const float*)d_in[5];
    const float* dw1 = (const float*)d_in[6];
    const float* db1 = (const float*)d_in[7];
    const float* dw2 = (const float*)d_in[8];
    const float* db2 = (const float*)d_in[9];
    const float* cb  = (const float*)d_in[10];
    float* out = (float*)d_out;

    cudaFuncSetAttribute(k_enc1, cudaFuncAttributeMaxDynamicSharedMemorySize, ENC_SM_BYTES);
    cudaFuncSetAttribute(k_vq2, cudaFuncAttributeMaxDynamicSharedMemorySize, SMEM_VQ_BYTES);

    k_setup<<<256, 256>>>(ew1);
    k_enc1<<<NPIX / 128, 256, ENC_SM_BYTES>>>(t0, t1, eb1);
    k_vq2<<<NTOK / VQ_TOKS, 256, SMEM_VQ_BYTES>>>(ew2, eb2, cb);
    k_dec<<<dim3(NTOK / 8, 2), 256>>>(dw1, db1, dw2, db2, cb, out);
    k_up<<<dim3(BATCH, HH), 256>>>(out);
}

// round 16
// speedup vs baseline: 1.8250x; 1.0345x over previous
#include <cuda_runtime.h>
#include <cuda_bf16.h>
#include <math.h>
#include <stdint.h>

// ---------------- problem constants ----------------
#define BATCH 512
#define HH 14
#define WW 14
#define DIN 512
#define EDIM 64
#define KCODES 256
#define NPIX (BATCH*HH*WW)          // 100352
#define NTOK (BATCH*4)              // 2048
#define H1 128                      // 2*EDIM

#define OUT_PPL ((size_t)NPIX*DIN)
#define OUT_CMT (OUT_PPL+1)
#define OUT_IDX (OUT_PPL+2)

// ---------------- scratch (static device memory; no allocations) ----------------
__device__ float g_Hbar[NTOK*H1];           // pooled SUMS (scaled by 1/49 in k_vq2)
__device__ float g_S[NTOK*DIN];
__device__ int   g_idx[NTOK];
__device__ int   g_counts[KCODES];
__device__ float g_loss;
// W1^T split into bf16 hi/lo: [n=128][k=512]
__device__ __nv_bfloat16 g_w1t_hi[H1*DIN];
__device__ __nv_bfloat16 g_w1t_lo[H1*DIN];

__device__ __forceinline__ float gelu_exact(float x) {
    return 0.5f * x * (1.0f + erff(x * 0.70710678118654752440f));
}

__device__ __forceinline__ uint32_t smem_u32(const void* p) {
    uint32_t a;
    asm("{ .reg .u64 t; cvta.to.shared.u64 t, %1; cvt.u32.u64 %0, t; }" : "=r"(a) : "l"(p));
    return a;
}

// baseline-PTX tensor ops (valid on plain sm_103 — no 'a' features)
__device__ __forceinline__ void ldsm_x4(uint32_t* r, uint32_t addr) {
    asm volatile("ldmatrix.sync.aligned.m8n8.x4.shared.b16 {%0,%1,%2,%3}, [%4];"
                 : "=r"(r[0]), "=r"(r[1]), "=r"(r[2]), "=r"(r[3]) : "r"(addr));
}
__device__ __forceinline__ void mma_bf16(float* d, const uint32_t* a, const uint32_t* b) {
    asm volatile("mma.sync.aligned.m16n8k16.row.col.f32.bf16.bf16.f32 "
                 "{%0,%1,%2,%3}, {%4,%5,%6,%7}, {%8,%9}, {%0,%1,%2,%3};"
                 : "+f"(d[0]), "+f"(d[1]), "+f"(d[2]), "+f"(d[3])
                 : "r"(a[0]), "r"(a[1]), "r"(a[2]), "r"(a[3]), "r"(b[0]), "r"(b[1]));
}
__device__ __forceinline__ uint32_t pk_bf16(__nv_bfloat16 a, __nv_bfloat16 b) {
    return (uint32_t)__bfloat16_as_ushort(a) | ((uint32_t)__bfloat16_as_ushort(b) << 16);
}
__device__ __forceinline__ void cp_async16(uint32_t dst, const void* src) {
    asm volatile("cp.async.ca.shared.global [%0], [%1], 16;" :: "r"(dst), "l"(src) : "memory");
}
#define CP_COMMIT()  asm volatile("cp.async.commit_group;" ::: "memory")
#define CP_WAIT0()   asm volatile("cp.async.wait_group 0;" ::: "memory")

// ---------------- kernel 0: setup (zero accumulators + Hbar, split W1^T) -----------
__global__ __launch_bounds__(256) void k_setup(const float* __restrict__ w1) {
    int idx = blockIdx.x * 256 + threadIdx.x;
    int k = idx >> 7, n = idx & 127;
    float v = w1[idx];
    __nv_bfloat16 hi = __float2bfloat16(v);
    __nv_bfloat16 lo = __float2bfloat16(v - __bfloat162float(hi));
    g_w1t_hi[n * DIN + k] = hi;
    g_w1t_lo[n * DIN + k] = lo;
    *(float4*)&g_Hbar[idx * 4] = make_float4(0.f, 0.f, 0.f, 0.f);
    if (blockIdx.x == 0) {
        g_counts[threadIdx.x] = 0;
        if (threadIdx.x == 0) g_loss = 0.0f;
    }
}

// ---------------- kernel 1: delta -> split-bf16 HMMA GEMM -> GELU -> fused pool ----
// (R11/R14 measured-best configuration — DO NOT grow registers or smem.)
#define SM_AHI 0
#define SM_ALO (128*144)
#define SM_BHI (2*128*144)
#define SM_BLO (3*128*144)
#define ENC_SM_BYTES (4*128*144)   // 73728
#define HS_PITCH 130

__global__ __launch_bounds__(256, 2) void k_enc1(const float* __restrict__ t0,
                                                 const float* __restrict__ t1,
                                                 const float* __restrict__ b1) {
    extern __shared__ char sm[];
    const uint32_t smb = smem_u32(sm);
    float* Hs = (float*)sm;
    const int tid = threadIdx.x;
    const int wid = tid >> 5, l = tid & 31;
    const int wm = wid & 3, wn = wid >> 2;
    const int p0 = blockIdx.x * 128;

    float acc[2][8][4];
#pragma unroll
    for (int rt = 0; rt < 2; rt++)
#pragma unroll
        for (int nt = 0; nt < 8; nt++)
#pragma unroll
            for (int q = 0; q < 4; q++) acc[rt][nt][q] = 0.0f;

    const uint32_t a_row = (uint32_t)(wm * 32 + (l & 15));
    const uint32_t a_kof = (uint32_t)((l >> 4) * 16);
    const uint32_t b_row4 = (uint32_t)(wn * 64 + ((l >> 4) << 3) + (l & 7));
    const uint32_t b_k4   = (uint32_t)(((l >> 3) & 1) * 16);

    for (int c = 0; c < 8; c++) {
        const int kc = c * 64;
        if (c) __syncthreads();
#pragma unroll
        for (int it = 0; it < 4; it++) {
            int i = tid + it * 256;
            int n = i >> 3, g = i & 7;
            uint32_t off = (uint32_t)(n * 144 + g * 16);
            cp_async16(smb + SM_BHI + off, g_w1t_hi + n * DIN + kc + g * 8);
            cp_async16(smb + SM_BLO + off, g_w1t_lo + n * DIN + kc + g * 8);
        }
        CP_COMMIT();
#pragma unroll
        for (int half = 0; half < 4; half++) {
            float4 v1[2], v0[2];
            int rows[2], gs[2];
#pragma unroll
            for (int u = 0; u < 2; u++) {
                int i = tid + (half * 2 + u) * 256;
                rows[u] = i >> 4; gs[u] = i & 15;
                size_t gaddr = (size_t)(p0 + rows[u]) * DIN + kc + gs[u] * 4;
                v1[u] = *(const float4*)(t1 + gaddr);
                v0[u] = *(const float4*)(t0 + gaddr);
            }
#pragma unroll
            for (int u = 0; u < 2; u++) {
                float d0 = v1[u].x - v0[u].x, d1 = v1[u].y - v0[u].y,
                      d2 = v1[u].z - v0[u].z, d3 = v1[u].w - v0[u].w;
                __nv_bfloat16 h0 = __float2bfloat16(d0), h1 = __float2bfloat16(d1),
                              h2 = __float2bfloat16(d2), h3 = __float2bfloat16(d3);
                __nv_bfloat16 e0 = __float2bfloat16(d0 - __bfloat162float(h0));
                __nv_bfloat16 e1 = __float2bfloat16(d1 - __bfloat162float(h1));
                __nv_bfloat16 e2 = __float2bfloat16(d2 - __bfloat162float(h2));
                __nv_bfloat16 e3 = __float2bfloat16(d3 - __bfloat162float(h3));
                uint32_t off = (uint32_t)(rows[u] * 144 + gs[u] * 8);
                *(uint2*)(sm + SM_AHI + off) = make_uint2(pk_bf16(h0, h1), pk_bf16(h2, h3));
                *(uint2*)(sm + SM_ALO + off) = make_uint2(pk_bf16(e0, e1), pk_bf16(e2, e3));
            }
        }
        CP_WAIT0();
        __syncthreads();
#pragma unroll
        for (int ks = 0; ks < 4; ks++) {
            uint32_t ahi[2][4], alo[2][4];
#pragma unroll
            for (int rt = 0; rt < 2; rt++) {
                uint32_t aoff = (a_row + rt * 16) * 144 + ks * 32 + a_kof;
                ldsm_x4(ahi[rt], smb + SM_AHI + aoff);
                ldsm_x4(alo[rt], smb + SM_ALO + aoff);
            }
#pragma unroll
            for (int ntp = 0; ntp < 4; ntp++) {
                uint32_t boff = (b_row4 + ntp * 16) * 144 + ks * 32 + b_k4;
                uint32_t bhi[4], blo[4];
                ldsm_x4(bhi, smb + SM_BHI + boff);
                ldsm_x4(blo, smb + SM_BLO + boff);
#pragma unroll
                for (int h = 0; h < 2; h++) {
                    int nt = ntp * 2 + h;
#pragma unroll
                    for (int rt = 0; rt < 2; rt++) {
                        mma_bf16(acc[rt][nt], ahi[rt], bhi + 2 * h);
                        mma_bf16(acc[rt][nt], ahi[rt], blo + 2 * h);
                        mma_bf16(acc[rt][nt], alo[rt], bhi + 2 * h);
                    }
                }
            }
        }
    }

    float2 bias[8];
#pragma unroll
    for (int nt = 0; nt < 8; nt++) {
        int cc = wn * 64 + nt * 8 + 2 * (l & 3);
        bias[nt] = make_float2(__ldg(&b1[cc]), __ldg(&b1[cc + 1]));
    }
    __syncthreads();
#pragma unroll
    for (int rt = 0; rt < 2; rt++) {
        int rl = wm * 32 + rt * 16 + (l >> 2);
#pragma unroll
        for (int nt = 0; nt < 8; nt++) {
            int cc = wn * 64 + nt * 8 + 2 * (l & 3);
            float2 o0, o1;
            o0.x = gelu_exact(acc[rt][nt][0] + bias[nt].x);
            o0.y = gelu_exact(acc[rt][nt][1] + bias[nt].y);
            o1.x = gelu_exact(acc[rt][nt][2] + bias[nt].x);
            o1.y = gelu_exact(acc[rt][nt][3] + bias[nt].y);
            *(float2*)&Hs[rl * HS_PITCH + cc]       = o0;
            *(float2*)&Hs[(rl + 8) * HS_PITCH + cc] = o1;
        }
    }
    __syncthreads();

    const int b0 = p0 / 196;
#pragma unroll
    for (int i = 0; i < 4; i++) {
        int pair = tid + i * 256;
        int slot = pair >> 7, col = pair & 127;
        int db = slot >> 2, ty = (slot >> 1) & 1, tx = slot & 1;
        int b = b0 + db;
        int base = b * 196 + ty * 98 + tx * 7 - p0;
        float s = 0.0f;
        int hit = 0;
#pragma unroll
        for (int dy = 0; dy < 7; dy++) {
            int rs = base + dy * 14;
            int lo = rs < 0 ? 0 : rs;
            int hi = rs + 7 > 128 ? 128 : rs + 7;
            for (int r = lo; r < hi; r++) { s += Hs[r * HS_PITCH + col]; hit = 1; }
        }
        if (hit) atomicAdd(&g_Hbar[(size_t)(b * 4 + ty * 2 + tx) * H1 + col], s);
    }
}

// ---------------- kernel 3: GEMM2 + VQ (8 tokens/block, 256 blocks) ----------------
#define VQ_TOKS 8
#define CBT_LD 257
#define FS_LD 65
#define SMEM_VQ_FLOATS (64*CBT_LD + VQ_TOKS*H1 + VQ_TOKS*FS_LD + KCODES + VQ_TOKS)
#define SMEM_VQ_BYTES (SMEM_VQ_FLOATS * 4)

__global__ __launch_bounds__(256) void k_vq2(const float* __restrict__ w2,
                                             const float* __restrict__ b2,
                                             const float* __restrict__ cb) {
    extern __shared__ float smv[];
    float* cbT   = smv;
    float* hbs   = cbT + 64 * CBT_LD;
    float* fs    = hbs + VQ_TOKS * H1;
    float* cn    = fs + VQ_TOKS * FS_LD;
    float* fnorm = cn + KCODES;

    const int tid = threadIdx.x;
    const int tok0 = blockIdx.x * VQ_TOKS;

    for (int li = tid; li < KCODES * EDIM; li += 256) {
        int c = li >> 6, j = li & 63;
        cbT[j * CBT_LD + c] = cb[li];
    }
    for (int li = tid; li < VQ_TOKS * H1; li += 256)
        hbs[li] = g_Hbar[tok0 * H1 + li] * (1.0f / 49.0f);
    __syncthreads();

    {
        float s = 0.0f;
#pragma unroll 8
        for (int j = 0; j < EDIM; j++) {
            float v = cbT[j * CBT_LD + tid];
            s = fmaf(v, v, s);
        }
        cn[tid] = s;
    }

    {
        const int j = tid & 63, tg = tid >> 6;
        float bj = b2[j];
        float acc0 = bj, acc1 = bj;
#pragma unroll 4
        for (int k = 0; k < H1; k++) {
            float wv = __ldg(&w2[k * EDIM + j]);
            acc0 = fmaf(hbs[(tg * 2 + 0) * H1 + k], wv, acc0);
            acc1 = fmaf(hbs[(tg * 2 + 1) * H1 + k], wv, acc1);
        }
        fs[(tg * 2 + 0) * FS_LD + j] = acc0;
        fs[(tg * 2 + 1) * FS_LD + j] = acc1;
    }
    __syncthreads();

    if (tid < VQ_TOKS) {
        float s = 0.0f;
#pragma unroll 8
        for (int j = 0; j < EDIM; j++) {
            float v = fs[tid * FS_LD + j];
            s = fmaf(v, v, s);
        }
        fnorm[tid] = s;
    }
    __syncthreads();

    const int w = tid >> 5, l = tid & 31;
    float dot[8];
#pragma unroll
    for (int i = 0; i < 8; i++) dot[i] = 0.0f;
#pragma unroll 4
    for (int j = 0; j < EDIM; j++) {
        float fj = fs[w * FS_LD + j];
#pragma unroll
        for (int i = 0; i < 8; i++)
            dot[i] = fmaf(fj, cbT[j * CBT_LD + l + 32 * i], dot[i]);
    }
    float bd = 3.4e38f; int bi = 0;
#pragma unroll
    for (int i = 0; i < 8; i++) {
        int c = l + 32 * i;
        float d = fmaf(-2.0f, dot[i], cn[c]);
        if (d < bd) { bd = d; bi = c; }
    }
    for (int off = 16; off > 0; off >>= 1) {
        float od = __shfl_down_sync(0xffffffffu, bd, off);
        int   oi = __shfl_down_sync(0xffffffffu, bi, off);
        if (od < bd || (od == bd && oi < bi)) { bd = od; bi = oi; }
    }
    if (l == 0) {
        int tok = tok0 + w;
        g_idx[tok] = bi;
        atomicAdd(&g_counts[bi], 1);
        atomicAdd(&g_loss, fnorm[w] + bd);
    }
}

// ---------------- kernel 5: decoder MLP (split over DIN halves) + fused finalize ----
// grid (256, 2). hd stored TRANSPOSED as hd2[k][8] so the dw2 loop reads it as
// 2 x LDS.128 broadcast per k (vs 8 x LDS.32) -> 4x fewer shared-load issues.
__global__ __launch_bounds__(256) void k_dec(const float* __restrict__ dw1,
                                             const float* __restrict__ db1,
                                             const float* __restrict__ dw2,
                                             const float* __restrict__ db2,
                                             const float* __restrict__ cb,
                                             float* __restrict__ out) {
    __shared__ float q[8][EDIM];
    __shared__ float hd2[H1 * 8];      // [k][tt]
    int tid = threadIdx.x;
    int tb = blockIdx.x * 8;
    int col = blockIdx.y * 256 + tid;

    for (int li = tid; li < 8 * EDIM; li += 256) {
        int tt = li >> 6, j = li & 63;
        q[tt][j] = cb[g_idx[tb + tt] * EDIM + j];
    }
    __syncthreads();
#pragma unroll
    for (int i = 0; i < 4; i++) {
        int li = tid + i * 256;
        int tt = li >> 7, j = li & 127;
        float s = db1[j];
#pragma unroll 8
        for (int k = 0; k < EDIM; k++) s = fmaf(q[tt][k], dw1[k * H1 + j], s);
        hd2[j * 8 + tt] = gelu_exact(s);
    }
    __syncthreads();

    float a[8];
#pragma unroll
    for (int tt = 0; tt < 8; tt++) a[tt] = 0.0f;
#pragma unroll 8
    for (int k = 0; k < H1; k++) {
        float w = __ldg(&dw2[k * DIN + col]);
        float4 h0 = *(const float4*)&hd2[k * 8];
        float4 h1 = *(const float4*)&hd2[k * 8 + 4];
        a[0] = fmaf(h0.x, w, a[0]); a[1] = fmaf(h0.y, w, a[1]);
        a[2] = fmaf(h0.z, w, a[2]); a[3] = fmaf(h0.w, w, a[3]);
        a[4] = fmaf(h1.x, w, a[4]); a[5] = fmaf(h1.y, w, a[5]);
        a[6] = fmaf(h1.z, w, a[6]); a[7] = fmaf(h1.w, w, a[7]);
    }
    float bb = __ldg(&db2[col]);
#pragma unroll
    for (int tt = 0; tt < 8; tt++)
        g_S[(size_t)(tb + tt) * DIN + col] = a[tt] + bb;

    // ---- fused finalize (block (0,0) only) ----
    if (blockIdx.x == 0 && blockIdx.y == 0) {
        __shared__ float r[256];
        float p = (float)g_counts[tid] * (1.0f / (float)NTOK);
        r[tid] = p * logf(p + 1e-10f);
        __syncthreads();
        for (int s = 128; s > 0; s >>= 1) {
            if (tid < s) r[tid] += r[tid + s];
            __syncthreads();
        }
        if (tid == 0) {
            out[OUT_PPL] = expf(-r[0]);
            out[OUT_CMT] = g_loss * (1.0f / (float)(NTOK * EDIM));
        }
        for (int i = tid; i < NTOK; i += 256) out[OUT_IDX + i] = (float)g_idx[i];
    }
}

// ---------------- kernel 6: 2x2 -> 14x14 bilinear (float4 path) ----------------
__global__ __launch_bounds__(256) void k_up(float* __restrict__ out) {
    __shared__ float Arow[DIN], Brow[DIN];
    int b = blockIdx.x, y = blockIdx.y;
    int tid = threadIdx.x;

    float sy = (y + 0.5f) * (1.0f / 7.0f) - 0.5f;
    int iy0 = (int)floorf(sy);
    float fy = sy - (float)iy0;
    int y0 = min(max(iy0, 0), 1);
    int y1 = min(max(iy0 + 1, 0), 1);

    const float* S0a = &g_S[(size_t)(b * 4 + y0 * 2 + 0) * DIN];
    const float* S1a = &g_S[(size_t)(b * 4 + y1 * 2 + 0) * DIN];
    const float* S0b = &g_S[(size_t)(b * 4 + y0 * 2 + 1) * DIN];
    const float* S1b = &g_S[(size_t)(b * 4 + y1 * 2 + 1) * DIN];
    float wy0 = 1.0f - fy;
    if (tid < 128) {
        int c4 = tid;
        float4 a0 = *(const float4*)&S0a[c4 * 4];
        float4 a1 = *(const float4*)&S1a[c4 * 4];
        float4 b0v = *(const float4*)&S0b[c4 * 4];
        float4 b1v = *(const float4*)&S1b[c4 * 4];
        float4 A, B;
        A.x = wy0 * a0.x + fy * a1.x; A.y = wy0 * a0.y + fy * a1.y;
        A.z = wy0 * a0.z + fy * a1.z; A.w = wy0 * a0.w + fy * a1.w;
        B.x = wy0 * b0v.x + fy * b1v.x; B.y = wy0 * b0v.y + fy * b1v.y;
        B.z = wy0 * b0v.z + fy * b1v.z; B.w = wy0 * b0v.w + fy * b1v.w;
        *(float4*)&Arow[c4 * 4] = A;
        *(float4*)&Brow[c4 * 4] = B;
    }
    __syncthreads();

    // 14 x-positions x 128 float4 = 1792 float4 stores, 7 per thread
#pragma unroll
    for (int i = 0; i < 7; i++) {
        int idx = tid + i * 256;
        int x = idx >> 7, c4 = idx & 127;
        float sx = (x + 0.5f) * (1.0f / 7.0f) - 0.5f;
        int ix0 = (int)floorf(sx);
        float fx = sx - (float)ix0;
        int x0 = min(max(ix0, 0), 1);
        int x1 = min(max(ix0 + 1, 0), 1);
        float wx0 = 1.0f - fx;
        float4 A = *(const float4*)&Arow[c4 * 4];
        float4 B = *(const float4*)&Brow[c4 * 4];
        float4 v0 = x0 ? B : A;
        float4 v1 = x1 ? B : A;
        float4 o;
        o.x = wx0 * v0.x + fx * v1.x;
        o.y = wx0 * v0.y + fx * v1.y;
        o.z = wx0 * v0.z + fx * v1.z;
        o.w = wx0 * v0.w + fx * v1.w;
        *(float4*)(out + ((size_t)((b * HH + y) * WW + x)) * DIN + c4 * 4) = o;
    }
}

// ---------------- launch ----------------
extern "C" void kernel_launch(void* const* d_in, const int* in_sizes, int n_in,
                              void* d_out, int out_size) {
    const float* t0  = (const float*)d_in[0];
    const float* t1  = (const float*)d_in[1];
    const float* ew1 = (const float*)d_in[2];
    const float* eb1 = (const float*)d_in[3];
    const float* ew2 = (const float*)d_in[4];
    const float* eb2 = (const float*)d_in[5];
    const float* dw1 = (const float*)d_in[6];
    const float* db1 = (const float*)d_in[7];
    const float* dw2 = (const float*)d_in[8];
    const float* db2 = (const float*)d_in[9];
    const float* cb  = (const float*)d_in[10];
    float* out = (float*)d_out;

    cudaFuncSetAttribute(k_enc1, cudaFuncAttributeMaxDynamicSharedMemorySize, ENC_SM_BYTES);
    cudaFuncSetAttribute(k_vq2, cudaFuncAttributeMaxDynamicSharedMemorySize, SMEM_VQ_BYTES);

    k_setup<<<256, 256>>>(ew1);
    k_enc1<<<NPIX / 128, 256, ENC_SM_BYTES>>>(t0, t1, eb1);
    k_vq2<<<NTOK / VQ_TOKS, 256, SMEM_VQ_BYTES>>>(ew2, eb2, cb);
    k_dec<<<dim3(NTOK / 8, 2), 256>>>(dw1, db1, dw2, db2, cb, out);
    k_up<<<dim3(BATCH, HH), 256>>>(out);
}

// round 17
// speedup vs baseline: 1.8798x; 1.0300x over previous
#include <cuda_runtime.h>
#include <cuda_bf16.h>
#include <math.h>
#include <stdint.h>

// ---------------- problem constants ----------------
#define BATCH 512
#define HH 14
#define WW 14
#define DIN 512
#define EDIM 64
#define KCODES 256
#define NPIX (BATCH*HH*WW)          // 100352
#define NTOK (BATCH*4)              // 2048
#define H1 128                      // 2*EDIM

#define OUT_PPL ((size_t)NPIX*DIN)
#define OUT_CMT (OUT_PPL+1)
#define OUT_IDX (OUT_PPL+2)

// ---------------- scratch (static device memory; no allocations) ----------------
__device__ float g_Hbar[NTOK*H1];           // pooled SUMS (scaled by 1/49 in k_vq2)
__device__ int   g_idx[NTOK];
__device__ int   g_counts[KCODES];
__device__ float g_loss;
// W1^T split into bf16 hi/lo: [n=128][k=512]
__device__ __nv_bfloat16 g_w1t_hi[H1*DIN];
__device__ __nv_bfloat16 g_w1t_lo[H1*DIN];
// decoder: transposed dw2 and per-code output table
__device__ float g_dw2t[DIN*H1];            // [col][k]
__device__ float g_table[KCODES*DIN];       // decoder output per code

__device__ __forceinline__ float gelu_exact(float x) {
    return 0.5f * x * (1.0f + erff(x * 0.70710678118654752440f));
}

__device__ __forceinline__ uint32_t smem_u32(const void* p) {
    uint32_t a;
    asm("{ .reg .u64 t; cvta.to.shared.u64 t, %1; cvt.u32.u64 %0, t; }" : "=r"(a) : "l"(p));
    return a;
}

// baseline-PTX tensor ops (valid on plain sm_103 — no 'a' features)
__device__ __forceinline__ void ldsm_x4(uint32_t* r, uint32_t addr) {
    asm volatile("ldmatrix.sync.aligned.m8n8.x4.shared.b16 {%0,%1,%2,%3}, [%4];"
                 : "=r"(r[0]), "=r"(r[1]), "=r"(r[2]), "=r"(r[3]) : "r"(addr));
}
__device__ __forceinline__ void mma_bf16(float* d, const uint32_t* a, const uint32_t* b) {
    asm volatile("mma.sync.aligned.m16n8k16.row.col.f32.bf16.bf16.f32 "
                 "{%0,%1,%2,%3}, {%4,%5,%6,%7}, {%8,%9}, {%0,%1,%2,%3};"
                 : "+f"(d[0]), "+f"(d[1]), "+f"(d[2]), "+f"(d[3])
                 : "r"(a[0]), "r"(a[1]), "r"(a[2]), "r"(a[3]), "r"(b[0]), "r"(b[1]));
}
__device__ __forceinline__ uint32_t pk_bf16(__nv_bfloat16 a, __nv_bfloat16 b) {
    return (uint32_t)__bfloat16_as_ushort(a) | ((uint32_t)__bfloat16_as_ushort(b) << 16);
}
__device__ __forceinline__ void cp_async16(uint32_t dst, const void* src) {
    asm volatile("cp.async.ca.shared.global [%0], [%1], 16;" :: "r"(dst), "l"(src) : "memory");
}
#define CP_COMMIT()  asm volatile("cp.async.commit_group;" ::: "memory")
#define CP_WAIT0()   asm volatile("cp.async.wait_group 0;" ::: "memory")

// ---------------- kernel 0: setup (zero accum + Hbar, split W1^T, transpose dw2) ----
__global__ __launch_bounds__(256) void k_setup(const float* __restrict__ w1,
                                               const float* __restrict__ dw2) {
    int idx = blockIdx.x * 256 + threadIdx.x;        // 0..65535
    int k = idx >> 7, n = idx & 127;
    float v = w1[idx];
    __nv_bfloat16 hi = __float2bfloat16(v);
    __nv_bfloat16 lo = __float2bfloat16(v - __bfloat162float(hi));
    g_w1t_hi[n * DIN + k] = hi;
    g_w1t_lo[n * DIN + k] = lo;
    *(float4*)&g_Hbar[idx * 4] = make_float4(0.f, 0.f, 0.f, 0.f);
    // transpose dw2 (128x512 -> [col][k]); coalesced read, scattered write
    int kk = idx >> 9, cc = idx & 511;
    g_dw2t[cc * H1 + kk] = dw2[idx];
    if (blockIdx.x == 0) {
        g_counts[threadIdx.x] = 0;
        if (threadIdx.x == 0) g_loss = 0.0f;
    }
}

// ---------------- kernel 1: delta -> split-bf16 HMMA GEMM -> GELU -> fused pool ----
// (R11/R14 measured-best configuration — DO NOT grow registers or smem.)
#define SM_AHI 0
#define SM_ALO (128*144)
#define SM_BHI (2*128*144)
#define SM_BLO (3*128*144)
#define ENC_SM_BYTES (4*128*144)   // 73728
#define HS_PITCH 130

__global__ __launch_bounds__(256, 2) void k_enc1(const float* __restrict__ t0,
                                                 const float* __restrict__ t1,
                                                 const float* __restrict__ b1) {
    extern __shared__ char sm[];
    const uint32_t smb = smem_u32(sm);
    float* Hs = (float*)sm;
    const int tid = threadIdx.x;
    const int wid = tid >> 5, l = tid & 31;
    const int wm = wid & 3, wn = wid >> 2;
    const int p0 = blockIdx.x * 128;

    float acc[2][8][4];
#pragma unroll
    for (int rt = 0; rt < 2; rt++)
#pragma unroll
        for (int nt = 0; nt < 8; nt++)
#pragma unroll
            for (int q = 0; q < 4; q++) acc[rt][nt][q] = 0.0f;

    const uint32_t a_row = (uint32_t)(wm * 32 + (l & 15));
    const uint32_t a_kof = (uint32_t)((l >> 4) * 16);
    const uint32_t b_row4 = (uint32_t)(wn * 64 + ((l >> 4) << 3) + (l & 7));
    const uint32_t b_k4   = (uint32_t)(((l >> 3) & 1) * 16);

    for (int c = 0; c < 8; c++) {
        const int kc = c * 64;
        if (c) __syncthreads();
#pragma unroll
        for (int it = 0; it < 4; it++) {
            int i = tid + it * 256;
            int n = i >> 3, g = i & 7;
            uint32_t off = (uint32_t)(n * 144 + g * 16);
            cp_async16(smb + SM_BHI + off, g_w1t_hi + n * DIN + kc + g * 8);
            cp_async16(smb + SM_BLO + off, g_w1t_lo + n * DIN + kc + g * 8);
        }
        CP_COMMIT();
#pragma unroll
        for (int half = 0; half < 4; half++) {
            float4 v1[2], v0[2];
            int rows[2], gs[2];
#pragma unroll
            for (int u = 0; u < 2; u++) {
                int i = tid + (half * 2 + u) * 256;
                rows[u] = i >> 4; gs[u] = i & 15;
                size_t gaddr = (size_t)(p0 + rows[u]) * DIN + kc + gs[u] * 4;
                v1[u] = *(const float4*)(t1 + gaddr);
                v0[u] = *(const float4*)(t0 + gaddr);
            }
#pragma unroll
            for (int u = 0; u < 2; u++) {
                float d0 = v1[u].x - v0[u].x, d1 = v1[u].y - v0[u].y,
                      d2 = v1[u].z - v0[u].z, d3 = v1[u].w - v0[u].w;
                __nv_bfloat16 h0 = __float2bfloat16(d0), h1 = __float2bfloat16(d1),
                              h2 = __float2bfloat16(d2), h3 = __float2bfloat16(d3);
                __nv_bfloat16 e0 = __float2bfloat16(d0 - __bfloat162float(h0));
                __nv_bfloat16 e1 = __float2bfloat16(d1 - __bfloat162float(h1));
                __nv_bfloat16 e2 = __float2bfloat16(d2 - __bfloat162float(h2));
                __nv_bfloat16 e3 = __float2bfloat16(d3 - __bfloat162float(h3));
                uint32_t off = (uint32_t)(rows[u] * 144 + gs[u] * 8);
                *(uint2*)(sm + SM_AHI + off) = make_uint2(pk_bf16(h0, h1), pk_bf16(h2, h3));
                *(uint2*)(sm + SM_ALO + off) = make_uint2(pk_bf16(e0, e1), pk_bf16(e2, e3));
            }
        }
        CP_WAIT0();
        __syncthreads();
#pragma unroll
        for (int ks = 0; ks < 4; ks++) {
            uint32_t ahi[2][4], alo[2][4];
#pragma unroll
            for (int rt = 0; rt < 2; rt++) {
                uint32_t aoff = (a_row + rt * 16) * 144 + ks * 32 + a_kof;
                ldsm_x4(ahi[rt], smb + SM_AHI + aoff);
                ldsm_x4(alo[rt], smb + SM_ALO + aoff);
            }
#pragma unroll
            for (int ntp = 0; ntp < 4; ntp++) {
                uint32_t boff = (b_row4 + ntp * 16) * 144 + ks * 32 + b_k4;
                uint32_t bhi[4], blo[4];
                ldsm_x4(bhi, smb + SM_BHI + boff);
                ldsm_x4(blo, smb + SM_BLO + boff);
#pragma unroll
                for (int h = 0; h < 2; h++) {
                    int nt = ntp * 2 + h;
#pragma unroll
                    for (int rt = 0; rt < 2; rt++) {
                        mma_bf16(acc[rt][nt], ahi[rt], bhi + 2 * h);
                        mma_bf16(acc[rt][nt], ahi[rt], blo + 2 * h);
                        mma_bf16(acc[rt][nt], alo[rt], bhi + 2 * h);
                    }
                }
            }
        }
    }

    float2 bias[8];
#pragma unroll
    for (int nt = 0; nt < 8; nt++) {
        int cc = wn * 64 + nt * 8 + 2 * (l & 3);
        bias[nt] = make_float2(__ldg(&b1[cc]), __ldg(&b1[cc + 1]));
    }
    __syncthreads();
#pragma unroll
    for (int rt = 0; rt < 2; rt++) {
        int rl = wm * 32 + rt * 16 + (l >> 2);
#pragma unroll
        for (int nt = 0; nt < 8; nt++) {
            int cc = wn * 64 + nt * 8 + 2 * (l & 3);
            float2 o0, o1;
            o0.x = gelu_exact(acc[rt][nt][0] + bias[nt].x);
            o0.y = gelu_exact(acc[rt][nt][1] + bias[nt].y);
            o1.x = gelu_exact(acc[rt][nt][2] + bias[nt].x);
            o1.y = gelu_exact(acc[rt][nt][3] + bias[nt].y);
            *(float2*)&Hs[rl * HS_PITCH + cc]       = o0;
            *(float2*)&Hs[(rl + 8) * HS_PITCH + cc] = o1;
        }
    }
    __syncthreads();

    const int b0 = p0 / 196;
#pragma unroll
    for (int i = 0; i < 4; i++) {
        int pair = tid + i * 256;
        int slot = pair >> 7, col = pair & 127;
        int db = slot >> 2, ty = (slot >> 1) & 1, tx = slot & 1;
        int b = b0 + db;
        int base = b * 196 + ty * 98 + tx * 7 - p0;
        float s = 0.0f;
        int hit = 0;
#pragma unroll
        for (int dy = 0; dy < 7; dy++) {
            int rs = base + dy * 14;
            int lo = rs < 0 ? 0 : rs;
            int hi = rs + 7 > 128 ? 128 : rs + 7;
            for (int r = lo; r < hi; r++) { s += Hs[r * HS_PITCH + col]; hit = 1; }
        }
        if (hit) atomicAdd(&g_Hbar[(size_t)(b * 4 + ty * 2 + tx) * H1 + col], s);
    }
}

// ---------------- kernel 3: GEMM2 + VQ (8 tokens/block, 256 blocks) ----------------
#define VQ_TOKS 8
#define CBT_LD 257
#define FS_LD 65
#define SMEM_VQ_FLOATS (64*CBT_LD + VQ_TOKS*H1 + VQ_TOKS*FS_LD + KCODES + VQ_TOKS)
#define SMEM_VQ_BYTES (SMEM_VQ_FLOATS * 4)

__global__ __launch_bounds__(256) void k_vq2(const float* __restrict__ w2,
                                             const float* __restrict__ b2,
                                             const float* __restrict__ cb) {
    extern __shared__ float smv[];
    float* cbT   = smv;
    float* hbs   = cbT + 64 * CBT_LD;
    float* fs    = hbs + VQ_TOKS * H1;
    float* cn    = fs + VQ_TOKS * FS_LD;
    float* fnorm = cn + KCODES;

    const int tid = threadIdx.x;
    const int tok0 = blockIdx.x * VQ_TOKS;

    for (int li = tid; li < KCODES * EDIM; li += 256) {
        int c = li >> 6, j = li & 63;
        cbT[j * CBT_LD + c] = cb[li];
    }
    for (int li = tid; li < VQ_TOKS * H1; li += 256)
        hbs[li] = g_Hbar[tok0 * H1 + li] * (1.0f / 49.0f);
    __syncthreads();

    {
        float s = 0.0f;
#pragma unroll 8
        for (int j = 0; j < EDIM; j++) {
            float v = cbT[j * CBT_LD + tid];
            s = fmaf(v, v, s);
        }
        cn[tid] = s;
    }

    {
        const int j = tid & 63, tg = tid >> 6;
        float bj = b2[j];
        float acc0 = bj, acc1 = bj;
#pragma unroll 4
        for (int k = 0; k < H1; k++) {
            float wv = __ldg(&w2[k * EDIM + j]);
            acc0 = fmaf(hbs[(tg * 2 + 0) * H1 + k], wv, acc0);
            acc1 = fmaf(hbs[(tg * 2 + 1) * H1 + k], wv, acc1);
        }
        fs[(tg * 2 + 0) * FS_LD + j] = acc0;
        fs[(tg * 2 + 1) * FS_LD + j] = acc1;
    }
    __syncthreads();

    if (tid < VQ_TOKS) {
        float s = 0.0f;
#pragma unroll 8
        for (int j = 0; j < EDIM; j++) {
            float v = fs[tid * FS_LD + j];
            s = fmaf(v, v, s);
        }
        fnorm[tid] = s;
    }
    __syncthreads();

    const int w = tid >> 5, l = tid & 31;
    float dot[8];
#pragma unroll
    for (int i = 0; i < 8; i++) dot[i] = 0.0f;
#pragma unroll 4
    for (int j = 0; j < EDIM; j++) {
        float fj = fs[w * FS_LD + j];
#pragma unroll
        for (int i = 0; i < 8; i++)
            dot[i] = fmaf(fj, cbT[j * CBT_LD + l + 32 * i], dot[i]);
    }
    float bd = 3.4e38f; int bi = 0;
#pragma unroll
    for (int i = 0; i < 8; i++) {
        int c = l + 32 * i;
        float d = fmaf(-2.0f, dot[i], cn[c]);
        if (d < bd) { bd = d; bi = c; }
    }
    for (int off = 16; off > 0; off >>= 1) {
        float od = __shfl_down_sync(0xffffffffu, bd, off);
        int   oi = __shfl_down_sync(0xffffffffu, bi, off);
        if (od < bd || (od == bd && oi < bi)) { bd = od; bi = oi; }
    }
    if (l == 0) {
        int tok = tok0 + w;
        g_idx[tok] = bi;
        atomicAdd(&g_counts[bi], 1);
        atomicAdd(&g_loss, fnorm[w] + bd);
    }
}

// ---------------- kernel 4: decoder TABLE (256 codes, not 2048 tokens) + finalize ---
// grid (32, 2): 8 codes x 256-col strip per block. Uses transposed dw2 so the
// k-loop is 32 independent LDG.128 per thread.
__global__ __launch_bounds__(256) void k_dectab(const float* __restrict__ dw1,
                                                const float* __restrict__ db1,
                                                const float* __restrict__ db2,
                                                const float* __restrict__ cb,
                                                float* __restrict__ out) {
    __shared__ float q[8][EDIM];
    __shared__ float hd2[H1 * 8];      // [k][code]
    int tid = threadIdx.x;
    int tb = blockIdx.x * 8;           // code base
    int col = blockIdx.y * 256 + tid;

    for (int li = tid; li < 8 * EDIM; li += 256) {
        int tt = li >> 6, j = li & 63;
        q[tt][j] = cb[(tb + tt) * EDIM + j];
    }
    __syncthreads();
#pragma unroll
    for (int i = 0; i < 4; i++) {
        int li = tid + i * 256;
        int tt = li >> 7, j = li & 127;
        float s = db1[j];
#pragma unroll 8
        for (int k = 0; k < EDIM; k++) s = fmaf(q[tt][k], dw1[k * H1 + j], s);
        hd2[j * 8 + tt] = gelu_exact(s);
    }
    __syncthreads();

    float a[8];
#pragma unroll
    for (int tt = 0; tt < 8; tt++) a[tt] = 0.0f;
    const float* wrow = g_dw2t + (size_t)col * H1;
#pragma unroll 8
    for (int kg = 0; kg < 32; kg++) {
        float4 w4 = *(const float4*)(wrow + kg * 4);
#pragma unroll
        for (int kk = 0; kk < 4; kk++) {
            float w = (kk == 0) ? w4.x : (kk == 1) ? w4.y : (kk == 2) ? w4.z : w4.w;
            int k = kg * 4 + kk;
            float4 h0 = *(const float4*)&hd2[k * 8];
            float4 h1 = *(const float4*)&hd2[k * 8 + 4];
            a[0] = fmaf(h0.x, w, a[0]); a[1] = fmaf(h0.y, w, a[1]);
            a[2] = fmaf(h0.z, w, a[2]); a[3] = fmaf(h0.w, w, a[3]);
            a[4] = fmaf(h1.x, w, a[4]); a[5] = fmaf(h1.y, w, a[5]);
            a[6] = fmaf(h1.z, w, a[6]); a[7] = fmaf(h1.w, w, a[7]);
        }
    }
    float bb = __ldg(&db2[col]);
#pragma unroll
    for (int tt = 0; tt < 8; tt++)
        g_table[(size_t)(tb + tt) * DIN + col] = a[tt] + bb;

    // ---- fused finalize (block (0,0) only) ----
    if (blockIdx.x == 0 && blockIdx.y == 0) {
        __shared__ float r[256];
        float p = (float)g_counts[tid] * (1.0f / (float)NTOK);
        r[tid] = p * logf(p + 1e-10f);
        __syncthreads();
        for (int s = 128; s > 0; s >>= 1) {
            if (tid < s) r[tid] += r[tid + s];
            __syncthreads();
        }
        if (tid == 0) {
            out[OUT_PPL] = expf(-r[0]);
            out[OUT_CMT] = g_loss * (1.0f / (float)(NTOK * EDIM));
        }
        for (int i = tid; i < NTOK; i += 256) out[OUT_IDX + i] = (float)g_idx[i];
    }
}

// ---------------- kernel 6: 2x2 -> 14x14 bilinear (gathers from code table) --------
__global__ __launch_bounds__(256) void k_up(float* __restrict__ out) {
    __shared__ float Arow[DIN], Brow[DIN];
    int b = blockIdx.x, y = blockIdx.y;
    int tid = threadIdx.x;

    float sy = (y + 0.5f) * (1.0f / 7.0f) - 0.5f;
    int iy0 = (int)floorf(sy);
    float fy = sy - (float)iy0;
    int y0 = min(max(iy0, 0), 1);
    int y1 = min(max(iy0 + 1, 0), 1);

    int4 id4 = *(const int4*)&g_idx[b * 4];   // tokens (gy,gx) = (0,0),(0,1),(1,0),(1,1)
    int i00 = id4.x, i01 = id4.y, i10 = id4.z, i11 = id4.w;
    int ia0 = y0 ? i10 : i00;     // (y0, x=0)
    int ia1 = y1 ? i10 : i00;     // (y1, x=0)
    int ib0 = y0 ? i11 : i01;     // (y0, x=1)
    int ib1 = y1 ? i11 : i01;     // (y1, x=1)
    const float* S0a = g_table + (size_t)ia0 * DIN;
    const float* S1a = g_table + (size_t)ia1 * DIN;
    const float* S0b = g_table + (size_t)ib0 * DIN;
    const float* S1b = g_table + (size_t)ib1 * DIN;

    float wy0 = 1.0f - fy;
    if (tid < 128) {
        int c4 = tid;
        float4 a0 = *(const float4*)&S0a[c4 * 4];
        float4 a1 = *(const float4*)&S1a[c4 * 4];
        float4 b0v = *(const float4*)&S0b[c4 * 4];
        float4 b1v = *(const float4*)&S1b[c4 * 4];
        float4 A, B;
        A.x = wy0 * a0.x + fy * a1.x; A.y = wy0 * a0.y + fy * a1.y;
        A.z = wy0 * a0.z + fy * a1.z; A.w = wy0 * a0.w + fy * a1.w;
        B.x = wy0 * b0v.x + fy * b1v.x; B.y = wy0 * b0v.y + fy * b1v.y;
        B.z = wy0 * b0v.z + fy * b1v.z; B.w = wy0 * b0v.w + fy * b1v.w;
        *(float4*)&Arow[c4 * 4] = A;
        *(float4*)&Brow[c4 * 4] = B;
    }
    __syncthreads();

#pragma unroll
    for (int i = 0; i < 7; i++) {
        int idx = tid + i * 256;
        int x = idx >> 7, c4 = idx & 127;
        float sx = (x + 0.5f) * (1.0f / 7.0f) - 0.5f;
        int ix0 = (int)floorf(sx);
        float fx = sx - (float)ix0;
        int x0 = min(max(ix0, 0), 1);
        int x1 = min(max(ix0 + 1, 0), 1);
        float wx0 = 1.0f - fx;
        float4 A = *(const float4*)&Arow[c4 * 4];
        float4 B = *(const float4*)&Brow[c4 * 4];
        float4 v0 = x0 ? B : A;
        float4 v1 = x1 ? B : A;
        float4 o;
        o.x = wx0 * v0.x + fx * v1.x;
        o.y = wx0 * v0.y + fx * v1.y;
        o.z = wx0 * v0.z + fx * v1.z;
        o.w = wx0 * v0.w + fx * v1.w;
        *(float4*)(out + ((size_t)((b * HH + y) * WW + x)) * DIN + c4 * 4) = o;
    }
}

// ---------------- launch ----------------
extern "C" void kernel_launch(void* const* d_in, const int* in_sizes, int n_in,
                              void* d_out, int out_size) {
    const float* t0  = (const float*)d_in[0];
    const float* t1  = (const float*)d_in[1];
    const float* ew1 = (const float*)d_in[2];
    const float* eb1 = (const float*)d_in[3];
    const float* ew2 = (const float*)d_in[4];
    const float* eb2 = (const float*)d_in[5];
    const float* dw1 = (const float*)d_in[6];
    const float* db1 = (const float*)d_in[7];
    const float* dw2 = (const float*)d_in[8];
    const float* db2 = (const float*)d_in[9];
    const float* cb  = (const float*)d_in[10];
    float* out = (float*)d_out;

    cudaFuncSetAttribute(k_enc1, cudaFuncAttributeMaxDynamicSharedMemorySize, ENC_SM_BYTES);
    cudaFuncSetAttribute(k_vq2, cudaFuncAttributeMaxDynamicSharedMemorySize, SMEM_VQ_BYTES);

    k_setup<<<256, 256>>>(ew1, dw2);
    k_enc1<<<NPIX / 128, 256, ENC_SM_BYTES>>>(t0, t1, eb1);
    k_vq2<<<NTOK / VQ_TOKS, 256, SMEM_VQ_BYTES>>>(ew2, eb2, cb);
    k_dectab<<<dim3(KCODES / 8, 2), 256>>>(dw1, db1, db2, cb, out);
    k_up<<<dim3(BATCH, HH), 256>>>(out);
}